// round 3
// baseline (speedup 1.0000x reference)
#include <cuda_runtime.h>
#include <math.h>

#define Nn 10000
#define Ee 160000

// ---------------- device scratch (allocation-free rule: __device__ globals) ----
__device__ __align__(16) float g_Y[(size_t)Ee * 16];
__device__ __align__(16) float g_bess[(size_t)Ee * 8];
__device__ __align__(16) float g_R[(size_t)Ee * 256];
__device__ __align__(16) float g_nfA[(size_t)Nn * 1024];
__device__ __align__(16) float g_nfB[(size_t)Nn * 1024];
__device__ __align__(16) float g_h[(size_t)Nn * 64];
__device__ int g_species[Nn];
__device__ int g_cnt[Nn];
__device__ int g_cursor[Nn];
__device__ int g_off[Nn + 1];
__device__ int g_eidx[Ee];
__device__ int g_sord[Ee];  // sender id per CSR-ordered edge (dependent-load cut)

__device__ __forceinline__ float silu_f(float x) { return x / (1.f + __expf(-x)); }

// ---- packed f32x2 helpers (Blackwell FFMA2; ptxas never auto-fuses these) ----
__device__ __forceinline__ unsigned long long pack2(float x, float y) {
    unsigned long long r;
    asm("mov.b64 %0, {%1, %2};" : "=l"(r) : "f"(x), "f"(y));
    return r;
}
__device__ __forceinline__ void unpack2(unsigned long long v, float& x, float& y) {
    asm("mov.b64 {%0, %1}, %2;" : "=f"(x), "=f"(y) : "l"(v));
}
__device__ __forceinline__ void ffma2(unsigned long long& acc, unsigned long long a,
                                      unsigned long long b) {
    asm("fma.rn.f32x2 %0, %1, %2, %0;" : "+l"(acc) : "l"(a), "l"(b));
}

// ---------------- geometry: Y (l=0..3) + bessel radial basis ------------------
__global__ void k_geom(const float* __restrict__ pos, const float* __restrict__ shifts,
                       const int* __restrict__ snd, const int* __restrict__ rcv) {
    int e = blockIdx.x * 256 + threadIdx.x;
    if (e >= Ee) return;
    int s = snd[e], r = rcv[e];
    float x = pos[r * 3 + 0] - pos[s * 3 + 0] + shifts[e * 3 + 0];
    float y = pos[r * 3 + 1] - pos[s * 3 + 1] + shifts[e * 3 + 1];
    float z = pos[r * 3 + 2] - pos[s * 3 + 2] + shifts[e * 3 + 2];
    float rr = sqrtf(x * x + y * y + z * z);
    float inv = 1.f / (rr + 1e-9f);
    float ux = x * inv, uy = y * inv, uz = z * inv;
    const float s3 = 1.7320508075688772f, s5 = 2.2360679774997896f, s7 = 2.6457513110645907f;
    const float s15 = 3.872983346207417f, s42 = 6.48074069840786f;
    const float s70 = 8.366600265340756f, s105 = 10.246950765959598f;
    float Y[16];
    Y[0] = 1.f;
    Y[1] = s3 * ux; Y[2] = s3 * uy; Y[3] = s3 * uz;
    Y[4] = s15 * ux * uy;
    Y[5] = s15 * uy * uz;
    Y[6] = 0.5f * s5 * (3.f * uz * uz - 1.f);
    Y[7] = s15 * ux * uz;
    Y[8] = 0.5f * s15 * (ux * ux - uy * uy);
    Y[9] = 0.25f * s70 * uy * (3.f * ux * ux - uy * uy);
    Y[10] = s105 * ux * uy * uz;
    Y[11] = 0.25f * s42 * uy * (5.f * uz * uz - 1.f);
    Y[12] = 0.5f * s7 * uz * (5.f * uz * uz - 3.f);
    Y[13] = 0.25f * s42 * ux * (5.f * uz * uz - 1.f);
    Y[14] = 0.5f * s105 * uz * (ux * ux - uy * uy);
    Y[15] = 0.25f * s70 * ux * (ux * ux - 3.f * uy * uy);
    float4* yo = (float4*)(g_Y + (size_t)e * 16);
    yo[0] = make_float4(Y[0], Y[1], Y[2], Y[3]);
    yo[1] = make_float4(Y[4], Y[5], Y[6], Y[7]);
    yo[2] = make_float4(Y[8], Y[9], Y[10], Y[11]);
    yo[3] = make_float4(Y[12], Y[13], Y[14], Y[15]);

    float xr = rr * 0.1f;
    float env = 0.f;
    if (xr < 1.f) {
        float x2 = xr * xr;
        float x4 = x2 * x2;
        float x5 = x4 * xr;
        env = 1.f - 21.f * x5 + 35.f * x5 * xr - 15.f * x5 * x2;
    }
    const float pref = 0.44721359549995793f;  // sqrt(2/RMAX)
    const float PIv = 3.14159265358979323846f;
#pragma unroll
    for (int n2 = 1; n2 <= 8; ++n2)
        g_bess[(size_t)e * 8 + (n2 - 1)] = pref * sinf((float)n2 * PIv * rr * 0.1f) * inv * env;
}

// ---------------- CSR build (deterministic: per-segment sorted) ---------------
__global__ void k_zero() {
    int i = blockIdx.x * 256 + threadIdx.x;
    if (i < Nn) { g_cnt[i] = 0; g_cursor[i] = 0; }
}
__global__ void k_count(const int* __restrict__ rcv) {
    int e = blockIdx.x * 256 + threadIdx.x;
    if (e < Ee) atomicAdd(&g_cnt[rcv[e]], 1);
}
__global__ void k_scan() {  // 1 block, 1024 threads; 10 chunks cover N=10000
    __shared__ int sm[1024];
    __shared__ int srun;
    int tid = threadIdx.x;
    if (tid == 0) srun = 0;
    __syncthreads();
    for (int c = 0; c < 10; ++c) {
        int i = c * 1024 + tid;
        int v = (i < Nn) ? g_cnt[i] : 0;
        sm[tid] = v;
        __syncthreads();
        for (int d = 1; d < 1024; d <<= 1) {
            int t = (tid >= d) ? sm[tid - d] : 0;
            __syncthreads();
            sm[tid] += t;
            __syncthreads();
        }
        int incl = sm[tid];
        int run = srun;
        if (i < Nn) g_off[i] = run + incl - v;
        __syncthreads();
        if (tid == 1023) srun = run + incl;
        __syncthreads();
    }
    if (tid == 0) g_off[Nn] = srun;
}
__global__ void k_fill(const int* __restrict__ rcv) {
    int e = blockIdx.x * 256 + threadIdx.x;
    if (e >= Ee) return;
    int r = rcv[e];
    int p = atomicAdd(&g_cursor[r], 1);
    g_eidx[g_off[r] + p] = e;
}
__global__ void k_sortseg() {
    int n = blockIdx.x * 256 + threadIdx.x;
    if (n >= Nn) return;
    int b = g_off[n], t = g_off[n + 1];
    for (int i = b + 1; i < t; ++i) {
        int key = g_eidx[i];
        int j = i - 1;
        while (j >= b && g_eidx[j] > key) { g_eidx[j + 1] = g_eidx[j]; --j; }
        g_eidx[j + 1] = key;
    }
}
__global__ void k_resolve(const int* __restrict__ snd) {
    int i = blockIdx.x * 256 + threadIdx.x;
    if (i < Ee) g_sord[i] = snd[g_eidx[i]];
}

// ---------------- node embedding + species index ------------------------------
__global__ void k_embed(const float* __restrict__ attrs, const float* __restrict__ wemb) {
    int n = blockIdx.x;
    int f = threadIdx.x;  // 64
    __shared__ int sp;
    if (f == 0) {
        int s = 0;
#pragma unroll
        for (int j = 0; j < 10; ++j)
            if (attrs[n * 10 + j] > 0.5f) s = j;
        sp = s;
        g_species[n] = s;
    }
    __syncthreads();
    g_nfA[(size_t)n * 1024 + f] = wemb[sp * 64 + f];
#pragma unroll
    for (int k = 1; k < 16; ++k) g_nfA[(size_t)n * 1024 + k * 64 + f] = 0.f;
}

// ---------------- h = nf[:,:,0] @ W_up ----------------------------------------
__global__ void k_h(int src, const float* __restrict__ Wup) {
    const float* nf = src ? g_nfB : g_nfA;
    int n = blockIdx.x;
    int f = threadIdx.x;  // 64
    __shared__ float row[64];
    row[f] = nf[(size_t)n * 1024 + f];
    __syncthreads();
    float acc = 0.f;
#pragma unroll 8
    for (int g = 0; g < 64; ++g) acc += row[g] * Wup[g * 64 + f];
    g_h[(size_t)n * 64 + f] = acc;
}

// ---------------- radial MLP: bess[E,8] -> silu -> silu -> R[E,256] -----------
// 64 edges/block, 256 threads. Static smem 45568 B. Layers 2/3 use packed FFMA2.
__global__ void __launch_bounds__(256) k_radial(const float* __restrict__ W1,
                                                const float* __restrict__ W2,
                                                const float* __restrict__ W3) {
    __shared__ __align__(16) float smem_f[11392];
    float* sb = smem_f;                                   // [64][8]
    float* w1s = smem_f + 512;                            // [8][64]
    float(*t1s)[65] = (float(*)[65])(smem_f + 1024);      // [64][65]
    float(*t2s)[65] = (float(*)[65])(smem_f + 1024 + 4160);
    float* wch = smem_f + 1024 + 8320;                    // 2048 floats (8 KB chunk)
    int tid = threadIdx.x;
    int e0 = blockIdx.x * 64;

    {   // stage bess tile + W1
        const float4* bsrc = (const float4*)(g_bess + (size_t)e0 * 8);
        float4* bdst = (float4*)sb;
        for (int i = tid; i < 128; i += 256) bdst[i] = bsrc[i];
        const float4* wsrc = (const float4*)W1;
        float4* wdst = (float4*)w1s;
        for (int i = tid; i < 128; i += 256) wdst[i] = wsrc[i];
    }
    __syncthreads();

    // layer 1: [64,8]@[8,64] -> silu -> t1s
#pragma unroll
    for (int i = 0; i < 16; ++i) {
        int o = tid + 256 * i;
        int e = o >> 6, c = o & 63;
        float acc = 0.f;
#pragma unroll
        for (int j = 0; j < 8; ++j) acc += sb[e * 8 + j] * w1s[j * 64 + c];
        t1s[e][c] = silu_f(acc);
    }

    // layer 2: [64,64]@[64,64] -> silu -> t2s. 4x4 register tiles (FFMA2 pairs).
    int ty2 = tid >> 4, tx2 = tid & 15;
    unsigned long long c2p[4][2] = {};
    for (int kc = 0; kc < 2; ++kc) {
        __syncthreads();
        {
            float4* d = (float4*)wch;
            const float4* s4 = ((const float4*)W2) + kc * 512;
            for (int i = tid; i < 512; i += 256) d[i] = s4[i];
        }
        __syncthreads();
#pragma unroll
        for (int kk = 0; kk < 32; ++kk) {
            int k = kc * 32 + kk;
            float4 b = *(const float4*)&wch[kk * 64 + tx2 * 4];
            unsigned long long b01 = pack2(b.x, b.y);
            unsigned long long b23 = pack2(b.z, b.w);
#pragma unroll
            for (int j = 0; j < 4; ++j) {
                float a = t1s[ty2 * 4 + j][k];
                unsigned long long aa = pack2(a, a);
                ffma2(c2p[j][0], aa, b01);
                ffma2(c2p[j][1], aa, b23);
            }
        }
    }
#pragma unroll
    for (int j = 0; j < 4; ++j) {
        float v0, v1, v2, v3;
        unpack2(c2p[j][0], v0, v1);
        unpack2(c2p[j][1], v2, v3);
        t2s[ty2 * 4 + j][tx2 * 4 + 0] = silu_f(v0);
        t2s[ty2 * 4 + j][tx2 * 4 + 1] = silu_f(v1);
        t2s[ty2 * 4 + j][tx2 * 4 + 2] = silu_f(v2);
        t2s[ty2 * 4 + j][tx2 * 4 + 3] = silu_f(v3);
    }

    // layer 3: [64,64]@[64,256] -> R. 8x8 register tiles, FFMA2-packed
    // (column pairs j = 2*j2, 2*j2+1 -> cols tx+64*j2, tx+32+64*j2).
    int ty = tid >> 5, tx = tid & 31;
    unsigned long long c3p[8][4] = {};
    for (int kc = 0; kc < 8; ++kc) {
        __syncthreads();
        {
            float4* d = (float4*)wch;
            const float4* s4 = ((const float4*)W3) + kc * 512;
            for (int i = tid; i < 512; i += 256) d[i] = s4[i];
        }
        __syncthreads();
#pragma unroll
        for (int kk = 0; kk < 8; ++kk) {
            int k = kc * 8 + kk;
            unsigned long long bp[4];
#pragma unroll
            for (int j2 = 0; j2 < 4; ++j2)
                bp[j2] = pack2(wch[kk * 256 + tx + 64 * j2], wch[kk * 256 + tx + 32 + 64 * j2]);
#pragma unroll
            for (int je = 0; je < 8; ++je) {
                float a = t2s[ty * 8 + je][k];
                unsigned long long aa = pack2(a, a);
#pragma unroll
                for (int j2 = 0; j2 < 4; ++j2) ffma2(c3p[je][j2], aa, bp[j2]);
            }
        }
    }
#pragma unroll
    for (int je = 0; je < 8; ++je) {
        size_t rb = ((size_t)(e0 + ty * 8 + je)) * 256;
#pragma unroll
        for (int j2 = 0; j2 < 4; ++j2) {
            float lo, hi;
            unpack2(c3p[je][j2], lo, hi);
            g_R[rb + tx + 64 * j2] = lo;
            g_R[rb + tx + 32 + 64 * j2] = hi;
        }
    }
}

// ---------------- gather + mix + product + self-connection --------------------
// One block per node. 256 threads: f = tid&63, kq = tid>>6 (4 k-channels each).
// L_OF = [0,1,1,1, 2,2,2,2, 2,3,3,3, 3,3,3,3]
__global__ void __launch_bounds__(256) k_gather(int src, const float* __restrict__ Wmix,
                                                const float* __restrict__ Wsc,
                                                const float* __restrict__ wprod,
                                                int last) {
    const float* nf_in = src ? g_nfB : g_nfA;
    float* nf_out = src ? g_nfA : g_nfB;
    int n = blockIdx.x;
    int tid = threadIdx.x;
    int f = tid & 63;
    int kq = tid >> 6;  // warp-uniform

    __shared__ __align__(16) float Asm[64][20];  // transposed A: [f][k], padded
    __shared__ __align__(16) float nfs[64][20];  // transposed nf_in
    __shared__ float ss[64];

    for (int i = tid; i < 1024; i += 256) {
        int k = i >> 6, ff = i & 63;
        nfs[ff][k] = nf_in[(size_t)n * 1024 + i];
    }

    float a0 = 0.f, a1 = 0.f, a2 = 0.f, a3 = 0.f;
    int beg = g_off[n], end = g_off[n + 1];
    for (int idx = beg; idx < end; ++idx) {
        int e = g_eidx[idx];
        int s = g_sord[idx];
        float hs = g_h[(size_t)s * 64 + f];
        float4 Rf = *(const float4*)(g_R + (size_t)e * 256 + f * 4);
        float4 Yv = *(const float4*)(g_Y + (size_t)e * 16 + kq * 4);
        float r0, r1, r2, r3;
        if (kq == 0)      { r0 = Rf.x; r1 = Rf.y; r2 = Rf.y; r3 = Rf.y; }
        else if (kq == 1) { r0 = Rf.z; r1 = Rf.z; r2 = Rf.z; r3 = Rf.z; }
        else if (kq == 2) { r0 = Rf.z; r1 = Rf.w; r2 = Rf.w; r3 = Rf.w; }
        else              { r0 = Rf.w; r1 = Rf.w; r2 = Rf.w; r3 = Rf.w; }
        a0 += hs * r0 * Yv.x;
        a1 += hs * r1 * Yv.y;
        a2 += hs * r2 * Yv.z;
        a3 += hs * r3 * Yv.w;
    }
    const float ia = 1.f / 16.f;  // AVG
    *(float4*)&Asm[f][kq * 4] = make_float4(a0 * ia, a1 * ia, a2 * ia, a3 * ia);
    __syncthreads();

    // mix: out[g,k] = sum_f A[f,k] * Wmix[l_k][f,g]
    int g = f;
    float o0 = 0.f, o1 = 0.f, o2 = 0.f, o3 = 0.f;
    if (kq == 0) {
#pragma unroll 4
        for (int ff = 0; ff < 64; ++ff) {
            float4 a = *(const float4*)&Asm[ff][0];
            float w0 = Wmix[ff * 64 + g];
            float w1 = Wmix[4096 + ff * 64 + g];
            o0 += a.x * w0; o1 += a.y * w1; o2 += a.z * w1; o3 += a.w * w1;
        }
    } else if (kq == 1) {
#pragma unroll 4
        for (int ff = 0; ff < 64; ++ff) {
            float4 a = *(const float4*)&Asm[ff][4];
            float w2 = Wmix[8192 + ff * 64 + g];
            o0 += a.x * w2; o1 += a.y * w2; o2 += a.z * w2; o3 += a.w * w2;
        }
    } else if (kq == 2) {
#pragma unroll 4
        for (int ff = 0; ff < 64; ++ff) {
            float4 a = *(const float4*)&Asm[ff][8];
            float w2 = Wmix[8192 + ff * 64 + g];
            float w3 = Wmix[12288 + ff * 64 + g];
            o0 += a.x * w2; o1 += a.y * w3; o2 += a.z * w3; o3 += a.w * w3;
        }
    } else {
#pragma unroll 4
        for (int ff = 0; ff < 64; ++ff) {
            float4 a = *(const float4*)&Asm[ff][12];
            float w3 = Wmix[12288 + ff * 64 + g];
            o0 += a.x * w3; o1 += a.y * w3; o2 += a.z * w3; o3 += a.w * w3;
        }
    }
    if (kq == 0) ss[g] = o0;  // s = mixed A[:,:,0]
    __syncthreads();

    // sc: sum_f nf_in[f,k] * Wsc[species][f,g]
    int sp = g_species[n];
    const float* Ws = Wsc + (size_t)sp * 4096;
    float c0 = 0.f, c1 = 0.f, c2v = 0.f, c3v = 0.f;
#pragma unroll 4
    for (int ff = 0; ff < 64; ++ff) {
        float4 a = *(const float4*)&nfs[ff][kq * 4];
        float w = Ws[ff * 64 + g];
        c0 += a.x * w; c1 += a.y * w; c2v += a.z * w; c3v += a.w * w;
    }

    float sv = ss[g];
    float pv = wprod[g] + wprod[64 + g] * sv + wprod[128 + g] * sv * sv;
    float q0 = o0 * pv + c0;
    float q1 = o1 * pv + c1;
    float q2 = o2 * pv + c2v;
    float q3 = o3 * pv + c3v;
    if (last) {
        if (kq != 0) { q0 = q1 = q2 = q3 = 0.f; }
        else { q1 = q2 = q3 = 0.f; }
    }
    size_t base = (size_t)n * 1024 + (size_t)(kq * 4) * 64 + g;
    nf_out[base] = q0;
    nf_out[base + 64] = q1;
    nf_out[base + 128] = q2;
    nf_out[base + 192] = q3;
}

// ---------------- readouts ----------------------------------------------------
__global__ void k_readout(const float* __restrict__ wr, const float* __restrict__ m1,
                          const float* __restrict__ m2, float* __restrict__ out) {
    int n = blockIdx.x;
    int f = threadIdx.x;  // 64
    __shared__ float red[64];
    __shared__ float row2[64];
    __shared__ float tt[16];
    red[f] = g_nfB[(size_t)n * 1024 + f] * wr[f];
    row2[f] = g_nfA[(size_t)n * 1024 + f];
    __syncthreads();
    for (int sdist = 32; sdist > 0; sdist >>= 1) {
        if (f < sdist) red[f] += red[f + sdist];
        __syncthreads();
    }
    if (f == 0) out[2 * n] = red[0];
    if (f < 16) {
        float a = 0.f;
#pragma unroll 8
        for (int ff = 0; ff < 64; ++ff) a += row2[ff] * m1[ff * 16 + f];
        tt[f] = silu_f(a);
    }
    __syncthreads();
    if (f == 0) {
        float a = 0.f;
#pragma unroll
        for (int j = 0; j < 16; ++j) a += tt[j] * m2[j];
        out[2 * n + 1] = a;
    }
}

// ---------------- host launch --------------------------------------------------
extern "C" void kernel_launch(void* const* d_in, const int* in_sizes, int n_in,
                              void* d_out, int out_size) {
    const float* positions = (const float*)d_in[0];
    const float* node_attrs = (const float*)d_in[1];
    const float* shifts = (const float*)d_in[2];
    const int* senders = (const int*)d_in[3];
    const int* receivers = (const int*)d_in[4];
    const float* w_embed = (const float*)d_in[5];

    const float *u_up[2], *u_r1[2], *u_r2[2], *u_r3[2], *u_mix[2], *u_sc[2], *u_prod[2];
    const float *w_read0, *w_mlp1, *w_mlp2;
    u_up[0] = (const float*)d_in[6];
    u_r1[0] = (const float*)d_in[7];
    u_r2[0] = (const float*)d_in[8];
    u_r3[0] = (const float*)d_in[9];
    u_mix[0] = (const float*)d_in[10];
    u_sc[0] = (const float*)d_in[11];
    u_prod[0] = (const float*)d_in[12];
    if (in_sizes[13] == 64) {
        // reference-signature order: w_read0 comes right after u0_prod
        w_read0 = (const float*)d_in[13];
        u_up[1] = (const float*)d_in[14];
        u_r1[1] = (const float*)d_in[15];
        u_r2[1] = (const float*)d_in[16];
        u_r3[1] = (const float*)d_in[17];
        u_mix[1] = (const float*)d_in[18];
        u_sc[1] = (const float*)d_in[19];
        u_prod[1] = (const float*)d_in[20];
        w_mlp1 = (const float*)d_in[21];
        w_mlp2 = (const float*)d_in[22];
    } else {
        // setup_inputs dict order: u1_* block, then w_read0, w_mlp1, w_mlp2
        u_up[1] = (const float*)d_in[13];
        u_r1[1] = (const float*)d_in[14];
        u_r2[1] = (const float*)d_in[15];
        u_r3[1] = (const float*)d_in[16];
        u_mix[1] = (const float*)d_in[17];
        u_sc[1] = (const float*)d_in[18];
        u_prod[1] = (const float*)d_in[19];
        w_read0 = (const float*)d_in[20];
        w_mlp1 = (const float*)d_in[21];
        w_mlp2 = (const float*)d_in[22];
    }
    float* out = (float*)d_out;

    const int EB = (Ee + 255) / 256;  // 625
    const int NB = (Nn + 255) / 256;  // 40

    // per-edge geometry + CSR (deterministic: segments sorted by edge id)
    k_geom<<<EB, 256>>>(positions, shifts, senders, receivers);
    k_zero<<<NB, 256>>>();
    k_count<<<EB, 256>>>(receivers);
    k_scan<<<1, 1024>>>();
    k_fill<<<EB, 256>>>(receivers);
    k_sortseg<<<NB, 256>>>();
    k_resolve<<<EB, 256>>>(senders);
    k_embed<<<Nn, 64>>>(node_attrs, w_embed);

    // interaction 0: in = A (embed), out = B
    k_h<<<Nn, 64>>>(0, u_up[0]);
    k_radial<<<Ee / 64, 256>>>(u_r1[0], u_r2[0], u_r3[0]);
    k_gather<<<Nn, 256>>>(0, u_mix[0], u_sc[0], u_prod[0], 0);

    // interaction 1: in = B, out = A (last -> only k=0 kept)
    k_h<<<Nn, 64>>>(1, u_up[1]);
    k_radial<<<Ee / 64, 256>>>(u_r1[1], u_r2[1], u_r3[1]);
    k_gather<<<Nn, 256>>>(1, u_mix[1], u_sc[1], u_prod[1], 1);

    // out[:,0] from nfB (post-interaction-0), out[:,1] from nfA (post-interaction-1)
    k_readout<<<Nn, 64>>>(w_read0, w_mlp1, w_mlp2, out);
}

// round 8
// speedup vs baseline: 1.0207x; 1.0207x over previous
#include <cuda_runtime.h>
#include <math.h>

#define Nn 10000
#define Ee 160000

// ---------------- device scratch (allocation-free rule: __device__ globals) ----
__device__ __align__(16) float g_Y[(size_t)Ee * 16];
__device__ __align__(16) float g_bess[(size_t)Ee * 8];
__device__ __align__(16) float g_R[(size_t)Ee * 256];
__device__ __align__(16) float g_nfA[(size_t)Nn * 1024];
__device__ __align__(16) float g_nfB[(size_t)Nn * 1024];
__device__ __align__(16) float g_h[(size_t)Nn * 64];
__device__ __align__(16) float g_W3p[2][16384];  // paired (col, col+32) fp32 images
__device__ int g_species[Nn];
__device__ int g_cnt[Nn];
__device__ int g_cursor[Nn];
__device__ int g_off[Nn + 1];
__device__ int g_eidx[Ee];
__device__ int g_sord[Ee];

__device__ __forceinline__ float silu_f(float x) {
    return __fdividef(x, 1.f + __expf(-x));
}

// ---- packed f32x2 helpers (Blackwell FFMA2; ptxas never auto-fuses these) ----
__device__ __forceinline__ unsigned long long pack2(float x, float y) {
    unsigned long long r;
    asm("mov.b64 %0, {%1, %2};" : "=l"(r) : "f"(x), "f"(y));
    return r;
}
__device__ __forceinline__ void unpack2(unsigned long long v, float& x, float& y) {
    asm("mov.b64 {%0, %1}, %2;" : "=f"(x), "=f"(y) : "l"(v));
}
__device__ __forceinline__ void ffma2(unsigned long long& acc, unsigned long long a,
                                      unsigned long long b) {
    asm("fma.rn.f32x2 %0, %1, %2, %0;" : "+l"(acc) : "l"(a), "l"(b));
}

// ---------------- geometry: Y (l=0..3) + bessel radial basis ------------------
__global__ void k_geom(const float* __restrict__ pos, const float* __restrict__ shifts,
                       const int* __restrict__ snd, const int* __restrict__ rcv) {
    int e = blockIdx.x * 256 + threadIdx.x;
    if (e >= Ee) return;
    int s = snd[e], r = rcv[e];
    float x = pos[r * 3 + 0] - pos[s * 3 + 0] + shifts[e * 3 + 0];
    float y = pos[r * 3 + 1] - pos[s * 3 + 1] + shifts[e * 3 + 1];
    float z = pos[r * 3 + 2] - pos[s * 3 + 2] + shifts[e * 3 + 2];
    float rr = sqrtf(x * x + y * y + z * z);
    float inv = 1.f / (rr + 1e-9f);
    float ux = x * inv, uy = y * inv, uz = z * inv;
    const float s3 = 1.7320508075688772f, s5 = 2.2360679774997896f, s7 = 2.6457513110645907f;
    const float s15 = 3.872983346207417f, s42 = 6.48074069840786f;
    const float s70 = 8.366600265340756f, s105 = 10.246950765959598f;
    float Y[16];
    Y[0] = 1.f;
    Y[1] = s3 * ux; Y[2] = s3 * uy; Y[3] = s3 * uz;
    Y[4] = s15 * ux * uy;
    Y[5] = s15 * uy * uz;
    Y[6] = 0.5f * s5 * (3.f * uz * uz - 1.f);
    Y[7] = s15 * ux * uz;
    Y[8] = 0.5f * s15 * (ux * ux - uy * uy);
    Y[9] = 0.25f * s70 * uy * (3.f * ux * ux - uy * uy);
    Y[10] = s105 * ux * uy * uz;
    Y[11] = 0.25f * s42 * uy * (5.f * uz * uz - 1.f);
    Y[12] = 0.5f * s7 * uz * (5.f * uz * uz - 3.f);
    Y[13] = 0.25f * s42 * ux * (5.f * uz * uz - 1.f);
    Y[14] = 0.5f * s105 * uz * (ux * ux - uy * uy);
    Y[15] = 0.25f * s70 * ux * (ux * ux - 3.f * uy * uy);
    float4* yo = (float4*)(g_Y + (size_t)e * 16);
    yo[0] = make_float4(Y[0], Y[1], Y[2], Y[3]);
    yo[1] = make_float4(Y[4], Y[5], Y[6], Y[7]);
    yo[2] = make_float4(Y[8], Y[9], Y[10], Y[11]);
    yo[3] = make_float4(Y[12], Y[13], Y[14], Y[15]);

    float xr = rr * 0.1f;
    float env = 0.f;
    if (xr < 1.f) {
        float x2 = xr * xr;
        float x5 = x2 * x2 * xr;
        env = 1.f - 21.f * x5 + 35.f * x5 * xr - 15.f * x5 * x2;
    }
    const float pref = 0.44721359549995793f;
    const float PIv = 3.14159265358979323846f;
#pragma unroll
    for (int n2 = 1; n2 <= 8; ++n2)
        g_bess[(size_t)e * 8 + (n2 - 1)] = pref * sinf((float)n2 * PIv * rr * 0.1f) * inv * env;
}

// ---------------- W3 prepack: pair columns (c, c+32) for FFMA2 b-operands ------
// layout: pair index = k*128 + j2*32 + tx  <->  cols (tx+64*j2, tx+32+64*j2)
__global__ void k_wprep3(const float* __restrict__ W3a, const float* __restrict__ W3b) {
    int i = blockIdx.x * 256 + threadIdx.x;
    if (i >= 8192) return;
    int k = i >> 7, p = i & 127;
    int j2 = p >> 5, tx = p & 31;
#pragma unroll
    for (int u = 0; u < 2; ++u) {
        const float* W3 = u ? W3b : W3a;
        g_W3p[u][2 * i] = W3[k * 256 + tx + 64 * j2];
        g_W3p[u][2 * i + 1] = W3[k * 256 + tx + 32 + 64 * j2];
    }
}

// ---------------- CSR build (deterministic: per-segment sorted) ---------------
__global__ void k_zero() {
    int i = blockIdx.x * 256 + threadIdx.x;
    if (i < Nn) { g_cnt[i] = 0; g_cursor[i] = 0; }
}
__global__ void k_count(const int* __restrict__ rcv) {
    int e = blockIdx.x * 256 + threadIdx.x;
    if (e < Ee) atomicAdd(&g_cnt[rcv[e]], 1);
}
__global__ void k_scan() {  // 1 block, 1024 threads; warp-shuffle scan, 10 nodes/thread
    int tid = threadIdx.x;
    int base = tid * 10;
    int v[10];
    int s = 0;
#pragma unroll
    for (int j = 0; j < 10; ++j) {
        int i = base + j;
        int c = (i < Nn) ? g_cnt[i] : 0;
        v[j] = s;
        s += c;
    }
    int lane = tid & 31, w = tid >> 5;
    int x = s;
#pragma unroll
    for (int d = 1; d < 32; d <<= 1) {
        int t = __shfl_up_sync(0xffffffffu, x, d);
        if (lane >= d) x += t;
    }
    __shared__ int ws[32];
    if (lane == 31) ws[w] = x;
    __syncthreads();
    if (w == 0) {
        int y = ws[lane];
#pragma unroll
        for (int d = 1; d < 32; d <<= 1) {
            int t = __shfl_up_sync(0xffffffffu, y, d);
            if (lane >= d) y += t;
        }
        ws[lane] = y;
    }
    __syncthreads();
    int excl = x - s + (w > 0 ? ws[w - 1] : 0);
#pragma unroll
    for (int j = 0; j < 10; ++j) {
        int i = base + j;
        if (i < Nn) g_off[i] = excl + v[j];
    }
    if (tid == 1023) g_off[Nn] = ws[31];
}
__global__ void k_fill(const int* __restrict__ rcv) {
    int e = blockIdx.x * 256 + threadIdx.x;
    if (e >= Ee) return;
    int r = rcv[e];
    int p = atomicAdd(&g_cursor[r], 1);
    g_eidx[g_off[r] + p] = e;
}
__global__ void k_sortseg() {
    int n = blockIdx.x * 256 + threadIdx.x;
    if (n >= Nn) return;
    int b = g_off[n], t = g_off[n + 1];
    for (int i = b + 1; i < t; ++i) {
        int key = g_eidx[i];
        int j = i - 1;
        while (j >= b && g_eidx[j] > key) { g_eidx[j + 1] = g_eidx[j]; --j; }
        g_eidx[j + 1] = key;
    }
}
__global__ void k_resolve(const int* __restrict__ snd) {
    int i = blockIdx.x * 256 + threadIdx.x;
    if (i < Ee) g_sord[i] = snd[g_eidx[i]];
}

// ---------------- node embedding + species index ------------------------------
__global__ void k_embed(const float* __restrict__ attrs, const float* __restrict__ wemb) {
    int n = blockIdx.x;
    int f = threadIdx.x;  // 64
    __shared__ int sp;
    if (f == 0) {
        int s = 0;
#pragma unroll
        for (int j = 0; j < 10; ++j)
            if (attrs[n * 10 + j] > 0.5f) s = j;
        sp = s;
        g_species[n] = s;
    }
    __syncthreads();
    g_nfA[(size_t)n * 1024 + f] = wemb[sp * 64 + f];
#pragma unroll
    for (int k = 1; k < 16; ++k) g_nfA[(size_t)n * 1024 + k * 64 + f] = 0.f;
}

// ---------------- h = nf[:,:,0] @ W_up ----------------------------------------
__global__ void k_h(int src, const float* __restrict__ Wup) {
    const float* nf = src ? g_nfB : g_nfA;
    int n = blockIdx.x;
    int f = threadIdx.x;  // 64
    __shared__ float row[64];
    row[f] = nf[(size_t)n * 1024 + f];
    __syncthreads();
    float acc = 0.f;
#pragma unroll 8
    for (int g = 0; g < 64; ++g) acc += row[g] * Wup[g * 64 + f];
    g_h[(size_t)n * 64 + f] = acc;
}

// ---------------- radial MLP: bess[E,8] -> silu -> silu -> R[E,256] -----------
// 64 edges/block, 256 threads. Static smem 47360 B.
// t1/t2 stored TRANSPOSED ([col][edge], pad 68) -> layer-3 a-loads are broadcast
// LDS.128; W3 comes pre-paired (g_W3p) -> b-loads are aligned LDS.64, no packs.
// Layer-2 b-pairs are adjacent in smem -> direct LDS.64, no packs.
__global__ void __launch_bounds__(256) k_radial(const float* __restrict__ W1,
                                                const float* __restrict__ W2, int u) {
    __shared__ __align__(16) float smem_f[11840];
    float* sb = smem_f;                                   // [64][9]   576
    float* w1s = smem_f + 576;                            // [8][64]   512
    float(*t1t)[68] = (float(*)[68])(smem_f + 1088);      // [64][68]  4352
    float(*t2t)[68] = (float(*)[68])(smem_f + 5440);      // [64][68]  4352
    float* wch = smem_f + 9792;                           // 2048 (8 KB chunk)
    int tid = threadIdx.x;
    int e0 = blockIdx.x * 64;

    {   // stage bess tile (padded rows) + W1
        for (int i = tid; i < 512; i += 256) {
            int e = i >> 3, j = i & 7;
            sb[e * 9 + j] = g_bess[(size_t)e0 * 8 + i];
        }
        for (int i = tid; i < 512; i += 256) w1s[i] = W1[i];
    }
    __syncthreads();

    // layer 1: [64,8]@[8,64] -> silu -> t1t[c][e]
#pragma unroll
    for (int i = 0; i < 16; ++i) {
        int o = tid + 256 * i;
        int e = o >> 6, c = o & 63;
        float acc = 0.f;
#pragma unroll
        for (int j = 0; j < 8; ++j) acc += sb[e * 9 + j] * w1s[j * 64 + c];
        t1t[c][e] = silu_f(acc);
    }

    // layer 2: [64,64]@[64,64] -> silu -> t2t. 4x4 register tiles (FFMA2 pairs).
    int ty2 = tid >> 4, tx2 = tid & 15;
    unsigned long long c2p[4][2] = {};
    for (int kc = 0; kc < 2; ++kc) {
        __syncthreads();
        {
            float4* d = (float4*)wch;
            const float4* s4 = ((const float4*)W2) + kc * 512;
            for (int i = tid; i < 512; i += 256) d[i] = s4[i];
        }
        __syncthreads();
#pragma unroll
        for (int kk = 0; kk < 32; ++kk) {
            int k = kc * 32 + kk;
            const unsigned long long* bp2 =
                (const unsigned long long*)&wch[kk * 64 + tx2 * 4];
            unsigned long long b01 = bp2[0];
            unsigned long long b23 = bp2[1];
            float4 av = *(const float4*)&t1t[k][ty2 * 4];
            float a_[4] = {av.x, av.y, av.z, av.w};
#pragma unroll
            for (int j = 0; j < 4; ++j) {
                unsigned long long aa = pack2(a_[j], a_[j]);
                ffma2(c2p[j][0], aa, b01);
                ffma2(c2p[j][1], aa, b23);
            }
        }
    }
#pragma unroll
    for (int j = 0; j < 4; ++j) {
        float v0, v1, v2, v3;
        unpack2(c2p[j][0], v0, v1);
        unpack2(c2p[j][1], v2, v3);
        t2t[tx2 * 4 + 0][ty2 * 4 + j] = silu_f(v0);
        t2t[tx2 * 4 + 1][ty2 * 4 + j] = silu_f(v1);
        t2t[tx2 * 4 + 2][ty2 * 4 + j] = silu_f(v2);
        t2t[tx2 * 4 + 3][ty2 * 4 + j] = silu_f(v3);
    }

    // layer 3: [64,64]@[64,256] -> R. 8 edges x 4 col-pairs per thread.
    // a: broadcast LDS.128 from t2t[k]; b: pre-paired LDS.64 from wch.
    int ty = tid >> 5, tx = tid & 31;
    unsigned long long c3p[8][4] = {};
    for (int kc = 0; kc < 8; ++kc) {
        __syncthreads();
        {
            float4* d = (float4*)wch;
            const float4* s4 = ((const float4*)(g_W3p[u])) + kc * 512;
            for (int i = tid; i < 512; i += 256) d[i] = s4[i];
        }
        __syncthreads();
        const unsigned long long* wp = (const unsigned long long*)wch;
#pragma unroll
        for (int kk = 0; kk < 8; ++kk) {
            int k = kc * 8 + kk;
            unsigned long long bp[4];
#pragma unroll
            for (int j2 = 0; j2 < 4; ++j2) bp[j2] = wp[kk * 128 + j2 * 32 + tx];
            float4 a01 = *(const float4*)&t2t[k][ty * 8];
            float4 a23 = *(const float4*)&t2t[k][ty * 8 + 4];
            float a_[8] = {a01.x, a01.y, a01.z, a01.w, a23.x, a23.y, a23.z, a23.w};
#pragma unroll
            for (int je = 0; je < 8; ++je) {
                unsigned long long aa = pack2(a_[je], a_[je]);
#pragma unroll
                for (int j2 = 0; j2 < 4; ++j2) ffma2(c3p[je][j2], aa, bp[j2]);
            }
        }
    }
#pragma unroll
    for (int je = 0; je < 8; ++je) {
        size_t rb = ((size_t)(e0 + ty * 8 + je)) * 256;
#pragma unroll
        for (int j2 = 0; j2 < 4; ++j2) {
            float lo, hi;
            unpack2(c3p[je][j2], lo, hi);
            g_R[rb + tx + 64 * j2] = lo;
            g_R[rb + tx + 32 + 64 * j2] = hi;
        }
    }
}

// ---------------- gather + mix + product + self-connection --------------------
// One block per node. 256 threads: f = tid&63, kq = tid>>6.
// L_OF = [0,1,1,1, 2,2,2,2, 2,3,3,3, 3,3,3,3]
__global__ void __launch_bounds__(256) k_gather(int src, const float* __restrict__ Wmix,
                                                const float* __restrict__ Wsc,
                                                const float* __restrict__ wprod,
                                                int last) {
    const float* nf_in = src ? g_nfB : g_nfA;
    float* nf_out = src ? g_nfA : g_nfB;
    int n = blockIdx.x;
    int tid = threadIdx.x;
    int f = tid & 63;
    int kq = tid >> 6;  // warp-uniform

    __shared__ __align__(16) float Asm[64][20];
    __shared__ __align__(16) float nfs[64][20];
    __shared__ float ss[64];

    for (int i = tid; i < 1024; i += 256) {
        int k = i >> 6, ff = i & 63;
        nfs[ff][k] = nf_in[(size_t)n * 1024 + i];
    }

    float a0 = 0.f, a1 = 0.f, a2 = 0.f, a3 = 0.f;
    int beg = g_off[n], end = g_off[n + 1];
    for (int idx = beg; idx < end; ++idx) {
        int e = g_eidx[idx];
        int s = g_sord[idx];
        float hs = g_h[(size_t)s * 64 + f];
        float4 Rf = *(const float4*)(g_R + (size_t)e * 256 + f * 4);
        float4 Yv = *(const float4*)(g_Y + (size_t)e * 16 + kq * 4);
        float r0, r1, r2, r3;
        if (kq == 0)      { r0 = Rf.x; r1 = Rf.y; r2 = Rf.y; r3 = Rf.y; }
        else if (kq == 1) { r0 = Rf.z; r1 = Rf.z; r2 = Rf.z; r3 = Rf.z; }
        else if (kq == 2) { r0 = Rf.z; r1 = Rf.w; r2 = Rf.w; r3 = Rf.w; }
        else              { r0 = Rf.w; r1 = Rf.w; r2 = Rf.w; r3 = Rf.w; }
        a0 += hs * r0 * Yv.x;
        a1 += hs * r1 * Yv.y;
        a2 += hs * r2 * Yv.z;
        a3 += hs * r3 * Yv.w;
    }
    const float ia = 1.f / 16.f;
    *(float4*)&Asm[f][kq * 4] = make_float4(a0 * ia, a1 * ia, a2 * ia, a3 * ia);
    __syncthreads();

    int g = f;
    float o0 = 0.f, o1 = 0.f, o2 = 0.f, o3 = 0.f;
    if (kq == 0) {
#pragma unroll 4
        for (int ff = 0; ff < 64; ++ff) {
            float4 a = *(const float4*)&Asm[ff][0];
            float w0 = Wmix[ff * 64 + g];
            float w1 = Wmix[4096 + ff * 64 + g];
            o0 += a.x * w0; o1 += a.y * w1; o2 += a.z * w1; o3 += a.w * w1;
        }
    } else if (kq == 1) {
#pragma unroll 4
        for (int ff = 0; ff < 64; ++ff) {
            float4 a = *(const float4*)&Asm[ff][4];
            float w2 = Wmix[8192 + ff * 64 + g];
            o0 += a.x * w2; o1 += a.y * w2; o2 += a.z * w2; o3 += a.w * w2;
        }
    } else if (kq == 2) {
#pragma unroll 4
        for (int ff = 0; ff < 64; ++ff) {
            float4 a = *(const float4*)&Asm[ff][8];
            float w2 = Wmix[8192 + ff * 64 + g];
            float w3 = Wmix[12288 + ff * 64 + g];
            o0 += a.x * w2; o1 += a.y * w3; o2 += a.z * w3; o3 += a.w * w3;
        }
    } else {
#pragma unroll 4
        for (int ff = 0; ff < 64; ++ff) {
            float4 a = *(const float4*)&Asm[ff][12];
            float w3 = Wmix[12288 + ff * 64 + g];
            o0 += a.x * w3; o1 += a.y * w3; o2 += a.z * w3; o3 += a.w * w3;
        }
    }
    if (kq == 0) ss[g] = o0;
    __syncthreads();

    int sp = g_species[n];
    const float* Ws = Wsc + (size_t)sp * 4096;
    float c0 = 0.f, c1 = 0.f, c2v = 0.f, c3v = 0.f;
#pragma unroll 4
    for (int ff = 0; ff < 64; ++ff) {
        float4 a = *(const float4*)&nfs[ff][kq * 4];
        float w = Ws[ff * 64 + g];
        c0 += a.x * w; c1 += a.y * w; c2v += a.z * w; c3v += a.w * w;
    }

    float sv = ss[g];
    float pv = wprod[g] + wprod[64 + g] * sv + wprod[128 + g] * sv * sv;
    float q0 = o0 * pv + c0;
    float q1 = o1 * pv + c1;
    float q2 = o2 * pv + c2v;
    float q3 = o3 * pv + c3v;
    if (last) {
        if (kq != 0) { q0 = q1 = q2 = q3 = 0.f; }
        else { q1 = q2 = q3 = 0.f; }
    }
    size_t base = (size_t)n * 1024 + (size_t)(kq * 4) * 64 + g;
    nf_out[base] = q0;
    nf_out[base + 64] = q1;
    nf_out[base + 128] = q2;
    nf_out[base + 192] = q3;
}

// ---------------- readouts ----------------------------------------------------
__global__ void k_readout(const float* __restrict__ wr, const float* __restrict__ m1,
                          const float* __restrict__ m2, float* __restrict__ out) {
    int n = blockIdx.x;
    int f = threadIdx.x;  // 64
    __shared__ float red[64];
    __shared__ float row2[64];
    __shared__ float tt[16];
    red[f] = g_nfB[(size_t)n * 1024 + f] * wr[f];
    row2[f] = g_nfA[(size_t)n * 1024 + f];
    __syncthreads();
    for (int sdist = 32; sdist > 0; sdist >>= 1) {
        if (f < sdist) red[f] += red[f + sdist];
        __syncthreads();
    }
    if (f == 0) out[2 * n] = red[0];
    if (f < 16) {
        float a = 0.f;
#pragma unroll 8
        for (int ff = 0; ff < 64; ++ff) a += row2[ff] * m1[ff * 16 + f];
        tt[f] = silu_f(a);
    }
    __syncthreads();
    if (f == 0) {
        float a = 0.f;
#pragma unroll
        for (int j = 0; j < 16; ++j) a += tt[j] * m2[j];
        out[2 * n + 1] = a;
    }
}

// ---------------- host launch --------------------------------------------------
extern "C" void kernel_launch(void* const* d_in, const int* in_sizes, int n_in,
                              void* d_out, int out_size) {
    const float* positions = (const float*)d_in[0];
    const float* node_attrs = (const float*)d_in[1];
    const float* shifts = (const float*)d_in[2];
    const int* senders = (const int*)d_in[3];
    const int* receivers = (const int*)d_in[4];
    const float* w_embed = (const float*)d_in[5];

    const float *u_up[2], *u_r1[2], *u_r2[2], *u_r3[2], *u_mix[2], *u_sc[2], *u_prod[2];
    const float *w_read0, *w_mlp1, *w_mlp2;
    u_up[0] = (const float*)d_in[6];
    u_r1[0] = (const float*)d_in[7];
    u_r2[0] = (const float*)d_in[8];
    u_r3[0] = (const float*)d_in[9];
    u_mix[0] = (const float*)d_in[10];
    u_sc[0] = (const float*)d_in[11];
    u_prod[0] = (const float*)d_in[12];
    if (in_sizes[13] == 64) {
        w_read0 = (const float*)d_in[13];
        u_up[1] = (const float*)d_in[14];
        u_r1[1] = (const float*)d_in[15];
        u_r2[1] = (const float*)d_in[16];
        u_r3[1] = (const float*)d_in[17];
        u_mix[1] = (const float*)d_in[18];
        u_sc[1] = (const float*)d_in[19];
        u_prod[1] = (const float*)d_in[20];
        w_mlp1 = (const float*)d_in[21];
        w_mlp2 = (const float*)d_in[22];
    } else {
        u_up[1] = (const float*)d_in[13];
        u_r1[1] = (const float*)d_in[14];
        u_r2[1] = (const float*)d_in[15];
        u_r3[1] = (const float*)d_in[16];
        u_mix[1] = (const float*)d_in[17];
        u_sc[1] = (const float*)d_in[18];
        u_prod[1] = (const float*)d_in[19];
        w_read0 = (const float*)d_in[20];
        w_mlp1 = (const float*)d_in[21];
        w_mlp2 = (const float*)d_in[22];
    }
    float* out = (float*)d_out;

    const int EB = (Ee + 255) / 256;  // 625
    const int NB = (Nn + 255) / 256;  // 40

    // k_radial placed at launch slot 4 = the ncu capture slot (evidence: round-3
    // profile caught the 4th launch).
    k_geom<<<EB, 256>>>(positions, shifts, senders, receivers);
    k_wprep3<<<32, 256>>>(u_r3[0], u_r3[1]);
    k_zero<<<NB, 256>>>();
    k_radial<<<Ee / 64, 256>>>(u_r1[0], u_r2[0], 0);
    k_count<<<EB, 256>>>(receivers);
    k_scan<<<1, 1024>>>();
    k_fill<<<EB, 256>>>(receivers);
    k_sortseg<<<NB, 256>>>();
    k_resolve<<<EB, 256>>>(senders);
    k_embed<<<Nn, 64>>>(node_attrs, w_embed);

    // interaction 0: in = A (embed), out = B
    k_h<<<Nn, 64>>>(0, u_up[0]);
    k_gather<<<Nn, 256>>>(0, u_mix[0], u_sc[0], u_prod[0], 0);

    // interaction 1: in = B, out = A (last -> only k=0 kept)
    k_h<<<Nn, 64>>>(1, u_up[1]);
    k_radial<<<Ee / 64, 256>>>(u_r1[1], u_r2[1], 1);
    k_gather<<<Nn, 256>>>(1, u_mix[1], u_sc[1], u_prod[1], 1);

    k_readout<<<Nn, 64>>>(w_read0, w_mlp1, w_mlp2, out);
}

// round 14
// speedup vs baseline: 1.0450x; 1.0238x over previous
#include <cuda_runtime.h>
#include <math.h>

#define Nn 10000
#define Ee 160000

// ---------------- device scratch (allocation-free rule: __device__ globals) ----
__device__ __align__(16) float g_Y[(size_t)Ee * 16];
__device__ __align__(16) float g_bess[(size_t)Ee * 8];
__device__ __align__(16) float g_R[(size_t)Ee * 256];
__device__ __align__(16) float g_nfA[(size_t)Nn * 1024];
__device__ __align__(16) float g_nfB[(size_t)Nn * 1024];
__device__ __align__(16) float g_h[(size_t)Nn * 64];
__device__ __align__(16) float g_W3p[2][16384];  // paired (col, col+32) fp32 images
__device__ __align__(16) int2 g_es[Ee];          // (edge id, sender id) per CSR slot
__device__ int g_species[Nn];
__device__ int g_cnt[Nn];
__device__ int g_cursor[Nn];
__device__ int g_off[Nn + 1];
__device__ int g_eidx[Ee];

__device__ __forceinline__ float silu_f(float x) {
    return __fdividef(x, 1.f + __expf(-x));
}

// ---- packed f32x2 helpers (Blackwell FFMA2; ptxas never auto-fuses these) ----
__device__ __forceinline__ unsigned long long pack2(float x, float y) {
    unsigned long long r;
    asm("mov.b64 %0, {%1, %2};" : "=l"(r) : "f"(x), "f"(y));
    return r;
}
__device__ __forceinline__ void unpack2(unsigned long long v, float& x, float& y) {
    asm("mov.b64 {%0, %1}, %2;" : "=f"(x), "=f"(y) : "l"(v));
}
__device__ __forceinline__ void ffma2(unsigned long long& acc, unsigned long long a,
                                      unsigned long long b) {
    asm("fma.rn.f32x2 %0, %1, %2, %0;" : "+l"(acc) : "l"(a), "l"(b));
}

// ---------------- geometry: Y (l=0..3) + bessel radial basis ------------------
__global__ void k_geom(const float* __restrict__ pos, const float* __restrict__ shifts,
                       const int* __restrict__ snd, const int* __restrict__ rcv) {
    int e = blockIdx.x * 256 + threadIdx.x;
    if (e >= Ee) return;
    int s = snd[e], r = rcv[e];
    float x = pos[r * 3 + 0] - pos[s * 3 + 0] + shifts[e * 3 + 0];
    float y = pos[r * 3 + 1] - pos[s * 3 + 1] + shifts[e * 3 + 1];
    float z = pos[r * 3 + 2] - pos[s * 3 + 2] + shifts[e * 3 + 2];
    float rr = sqrtf(x * x + y * y + z * z);
    float inv = 1.f / (rr + 1e-9f);
    float ux = x * inv, uy = y * inv, uz = z * inv;
    const float s3 = 1.7320508075688772f, s5 = 2.2360679774997896f, s7 = 2.6457513110645907f;
    const float s15 = 3.872983346207417f, s42 = 6.48074069840786f;
    const float s70 = 8.366600265340756f, s105 = 10.246950765959598f;
    float Y[16];
    Y[0] = 1.f;
    Y[1] = s3 * ux; Y[2] = s3 * uy; Y[3] = s3 * uz;
    Y[4] = s15 * ux * uy;
    Y[5] = s15 * uy * uz;
    Y[6] = 0.5f * s5 * (3.f * uz * uz - 1.f);
    Y[7] = s15 * ux * uz;
    Y[8] = 0.5f * s15 * (ux * ux - uy * uy);
    Y[9] = 0.25f * s70 * uy * (3.f * ux * ux - uy * uy);
    Y[10] = s105 * ux * uy * uz;
    Y[11] = 0.25f * s42 * uy * (5.f * uz * uz - 1.f);
    Y[12] = 0.5f * s7 * uz * (5.f * uz * uz - 3.f);
    Y[13] = 0.25f * s42 * ux * (5.f * uz * uz - 1.f);
    Y[14] = 0.5f * s105 * uz * (ux * ux - uy * uy);
    Y[15] = 0.25f * s70 * ux * (ux * ux - 3.f * uy * uy);
    float4* yo = (float4*)(g_Y + (size_t)e * 16);
    yo[0] = make_float4(Y[0], Y[1], Y[2], Y[3]);
    yo[1] = make_float4(Y[4], Y[5], Y[6], Y[7]);
    yo[2] = make_float4(Y[8], Y[9], Y[10], Y[11]);
    yo[3] = make_float4(Y[12], Y[13], Y[14], Y[15]);

    float xr = rr * 0.1f;
    float env = 0.f;
    if (xr < 1.f) {
        float x2 = xr * xr;
        float x5 = x2 * x2 * xr;
        env = 1.f - 21.f * x5 + 35.f * x5 * xr - 15.f * x5 * x2;
    }
    const float pref = 0.44721359549995793f;
    const float PIv = 3.14159265358979323846f;
#pragma unroll
    for (int n2 = 1; n2 <= 8; ++n2)
        g_bess[(size_t)e * 8 + (n2 - 1)] = pref * sinf((float)n2 * PIv * rr * 0.1f) * inv * env;
}

// ---------------- W3 prepack: pair columns (c, c+32) for FFMA2 b-operands ------
// layout: pair index = k*128 + j2*32 + tx  <->  cols (tx+64*j2, tx+32+64*j2)
__global__ void k_wprep3(const float* __restrict__ W3a, const float* __restrict__ W3b) {
    int i = blockIdx.x * 256 + threadIdx.x;
    if (i >= 8192) return;
    int k = i >> 7, p = i & 127;
    int j2 = p >> 5, tx = p & 31;
#pragma unroll
    for (int u = 0; u < 2; ++u) {
        const float* W3 = u ? W3b : W3a;
        g_W3p[u][2 * i] = W3[k * 256 + tx + 64 * j2];
        g_W3p[u][2 * i + 1] = W3[k * 256 + tx + 32 + 64 * j2];
    }
}

// ---------------- CSR build (deterministic: per-segment sorted) ---------------
__global__ void k_zero() {
    int i = blockIdx.x * 256 + threadIdx.x;
    if (i < Nn) { g_cnt[i] = 0; g_cursor[i] = 0; }
}
__global__ void k_count(const int* __restrict__ rcv) {
    int e = blockIdx.x * 256 + threadIdx.x;
    if (e < Ee) atomicAdd(&g_cnt[rcv[e]], 1);
}
__global__ void k_scan() {  // 1 block, 1024 threads; warp-shuffle scan, 10 nodes/thread
    int tid = threadIdx.x;
    int base = tid * 10;
    int v[10];
    int s = 0;
#pragma unroll
    for (int j = 0; j < 10; ++j) {
        int i = base + j;
        int c = (i < Nn) ? g_cnt[i] : 0;
        v[j] = s;
        s += c;
    }
    int lane = tid & 31, w = tid >> 5;
    int x = s;
#pragma unroll
    for (int d = 1; d < 32; d <<= 1) {
        int t = __shfl_up_sync(0xffffffffu, x, d);
        if (lane >= d) x += t;
    }
    __shared__ int ws[32];
    if (lane == 31) ws[w] = x;
    __syncthreads();
    if (w == 0) {
        int y = ws[lane];
#pragma unroll
        for (int d = 1; d < 32; d <<= 1) {
            int t = __shfl_up_sync(0xffffffffu, y, d);
            if (lane >= d) y += t;
        }
        ws[lane] = y;
    }
    __syncthreads();
    int excl = x - s + (w > 0 ? ws[w - 1] : 0);
#pragma unroll
    for (int j = 0; j < 10; ++j) {
        int i = base + j;
        if (i < Nn) g_off[i] = excl + v[j];
    }
    if (tid == 1023) g_off[Nn] = ws[31];
}
__global__ void k_fill(const int* __restrict__ rcv) {
    int e = blockIdx.x * 256 + threadIdx.x;
    if (e >= Ee) return;
    int r = rcv[e];
    int p = atomicAdd(&g_cursor[r], 1);
    g_eidx[g_off[r] + p] = e;
}
__global__ void k_sortseg() {
    int n = blockIdx.x * 256 + threadIdx.x;
    if (n >= Nn) return;
    int b = g_off[n], t = g_off[n + 1];
    for (int i = b + 1; i < t; ++i) {
        int key = g_eidx[i];
        int j = i - 1;
        while (j >= b && g_eidx[j] > key) { g_eidx[j + 1] = g_eidx[j]; --j; }
        g_eidx[j + 1] = key;
    }
}
__global__ void k_resolve(const int* __restrict__ snd) {
    int i = blockIdx.x * 256 + threadIdx.x;
    if (i < Ee) {
        int e = g_eidx[i];
        g_es[i] = make_int2(e, snd[e]);
    }
}

// ---------------- node embedding + species index ------------------------------
__global__ void k_embed(const float* __restrict__ attrs, const float* __restrict__ wemb) {
    int n = blockIdx.x;
    int f = threadIdx.x;  // 64
    __shared__ int sp;
    if (f == 0) {
        int s = 0;
#pragma unroll
        for (int j = 0; j < 10; ++j)
            if (attrs[n * 10 + j] > 0.5f) s = j;
        sp = s;
        g_species[n] = s;
    }
    __syncthreads();
    g_nfA[(size_t)n * 1024 + f] = wemb[sp * 64 + f];
#pragma unroll
    for (int k = 1; k < 16; ++k) g_nfA[(size_t)n * 1024 + k * 64 + f] = 0.f;
}

// ---------------- h = nf[:,:,0] @ W_up ----------------------------------------
__global__ void k_h(int src, const float* __restrict__ Wup) {
    const float* nf = src ? g_nfB : g_nfA;
    int n = blockIdx.x;
    int f = threadIdx.x;  // 64
    __shared__ float row[64];
    row[f] = nf[(size_t)n * 1024 + f];
    __syncthreads();
    float acc = 0.f;
#pragma unroll 8
    for (int g = 0; g < 64; ++g) acc += row[g] * Wup[g * 64 + f];
    g_h[(size_t)n * 64 + f] = acc;
}

// ---------------- radial MLP: bess[E,8] -> silu -> silu -> R[E,256] -----------
// 64 edges/block, 256 threads. Static smem 29952 B -> 3 blocks/SM (was 47.3KB/2).
// t1/t2 SHARE one transposed buffer ([col][edge], pad 68): layer-2 accumulators
// live in registers, so t1 reads finish (sync) before t2 overwrites the tile.
__global__ void __launch_bounds__(256, 3) k_radial(const float* __restrict__ W1,
                                                   const float* __restrict__ W2, int u) {
    __shared__ __align__(16) float smem_f[7488];
    float* sb = smem_f;                                   // [64][9]   576
    float* w1s = smem_f + 576;                            // [8][64]   512
    float(*tt)[68] = (float(*)[68])(smem_f + 1088);       // [64][68]  4352 (t1 then t2)
    float* wch = smem_f + 5440;                           // 2048 (8 KB chunk)
    int tid = threadIdx.x;
    int e0 = blockIdx.x * 64;

    {   // stage bess tile (padded rows) + W1
        for (int i = tid; i < 512; i += 256) {
            int e = i >> 3, j = i & 7;
            sb[e * 9 + j] = g_bess[(size_t)e0 * 8 + i];
        }
        for (int i = tid; i < 512; i += 256) w1s[i] = W1[i];
    }
    __syncthreads();

    // layer 1: [64,8]@[8,64] -> silu -> tt[c][e]  (t1 phase)
#pragma unroll
    for (int i = 0; i < 16; ++i) {
        int o = tid + 256 * i;
        int e = o >> 6, c = o & 63;
        float acc = 0.f;
#pragma unroll
        for (int j = 0; j < 8; ++j) acc += sb[e * 9 + j] * w1s[j * 64 + c];
        tt[c][e] = silu_f(acc);
    }

    // layer 2: [64,64]@[64,64]. 4x4 register tiles (FFMA2 pairs), acc in regs.
    int ty2 = tid >> 4, tx2 = tid & 15;
    unsigned long long c2p[4][2] = {};
    for (int kc = 0; kc < 2; ++kc) {
        __syncthreads();
        {
            float4* d = (float4*)wch;
            const float4* s4 = ((const float4*)W2) + kc * 512;
            for (int i = tid; i < 512; i += 256) d[i] = s4[i];
        }
        __syncthreads();
#pragma unroll
        for (int kk = 0; kk < 32; ++kk) {
            int k = kc * 32 + kk;
            const unsigned long long* bp2 =
                (const unsigned long long*)&wch[kk * 64 + tx2 * 4];
            unsigned long long b01 = bp2[0];
            unsigned long long b23 = bp2[1];
            float4 av = *(const float4*)&tt[k][ty2 * 4];
            float a_[4] = {av.x, av.y, av.z, av.w};
#pragma unroll
            for (int j = 0; j < 4; ++j) {
                unsigned long long aa = pack2(a_[j], a_[j]);
                ffma2(c2p[j][0], aa, b01);
                ffma2(c2p[j][1], aa, b23);
            }
        }
    }
    __syncthreads();  // all t1 reads done -> safe to overwrite tt with t2
#pragma unroll
    for (int j = 0; j < 4; ++j) {
        float v0, v1, v2, v3;
        unpack2(c2p[j][0], v0, v1);
        unpack2(c2p[j][1], v2, v3);
        tt[tx2 * 4 + 0][ty2 * 4 + j] = silu_f(v0);
        tt[tx2 * 4 + 1][ty2 * 4 + j] = silu_f(v1);
        tt[tx2 * 4 + 2][ty2 * 4 + j] = silu_f(v2);
        tt[tx2 * 4 + 3][ty2 * 4 + j] = silu_f(v3);
    }

    // layer 3: [64,64]@[64,256] -> R. 8 edges x 4 col-pairs per thread.
    // a: broadcast LDS.128 from tt[k] (t2 phase); b: pre-paired LDS.64 from wch.
    int ty = tid >> 5, tx = tid & 31;
    unsigned long long c3p[8][4] = {};
    for (int kc = 0; kc < 8; ++kc) {
        __syncthreads();
        {
            float4* d = (float4*)wch;
            const float4* s4 = ((const float4*)(g_W3p[u])) + kc * 512;
            for (int i = tid; i < 512; i += 256) d[i] = s4[i];
        }
        __syncthreads();
        const unsigned long long* wp = (const unsigned long long*)wch;
#pragma unroll
        for (int kk = 0; kk < 8; ++kk) {
            int k = kc * 8 + kk;
            unsigned long long bp[4];
#pragma unroll
            for (int j2 = 0; j2 < 4; ++j2) bp[j2] = wp[kk * 128 + j2 * 32 + tx];
            float4 a01 = *(const float4*)&tt[k][ty * 8];
            float4 a23 = *(const float4*)&tt[k][ty * 8 + 4];
            float a_[8] = {a01.x, a01.y, a01.z, a01.w, a23.x, a23.y, a23.z, a23.w};
#pragma unroll
            for (int je = 0; je < 8; ++je) {
                unsigned long long aa = pack2(a_[je], a_[je]);
#pragma unroll
                for (int j2 = 0; j2 < 4; ++j2) ffma2(c3p[je][j2], aa, bp[j2]);
            }
        }
    }
#pragma unroll
    for (int je = 0; je < 8; ++je) {
        size_t rb = ((size_t)(e0 + ty * 8 + je)) * 256;
#pragma unroll
        for (int j2 = 0; j2 < 4; ++j2) {
            float lo, hi;
            unpack2(c3p[je][j2], lo, hi);
            g_R[rb + tx + 64 * j2] = lo;
            g_R[rb + tx + 32 + 64 * j2] = hi;
        }
    }
}

// ---------------- gather + mix + product + self-connection --------------------
// One block per node. 256 threads: f = tid&63, kq = tid>>6.
// Edge loop unrolled x2: two independent gather sets in flight (MLP 1 -> 2).
// L_OF = [0,1,1,1, 2,2,2,2, 2,3,3,3, 3,3,3,3]
__global__ void __launch_bounds__(256) k_gather(int src, const float* __restrict__ Wmix,
                                                const float* __restrict__ Wsc,
                                                const float* __restrict__ wprod,
                                                int last) {
    const float* nf_in = src ? g_nfB : g_nfA;
    float* nf_out = src ? g_nfA : g_nfB;
    int n = blockIdx.x;
    int tid = threadIdx.x;
    int f = tid & 63;
    int kq = tid >> 6;  // warp-uniform

    __shared__ __align__(16) float Asm[64][20];
    __shared__ __align__(16) float nfs[64][20];
    __shared__ float ss[64];

    for (int i = tid; i < 1024; i += 256) {
        int k = i >> 6, ff = i & 63;
        nfs[ff][k] = nf_in[(size_t)n * 1024 + i];
    }

    float a0 = 0.f, a1 = 0.f, a2 = 0.f, a3 = 0.f;
    int beg = g_off[n], end = g_off[n + 1];
    int idx = beg;
    for (; idx + 1 < end; idx += 2) {
        int2 es0 = g_es[idx];
        int2 es1 = g_es[idx + 1];
        float hs0 = g_h[(size_t)es0.y * 64 + f];
        float hs1 = g_h[(size_t)es1.y * 64 + f];
        float4 Rf0 = *(const float4*)(g_R + (size_t)es0.x * 256 + f * 4);
        float4 Rf1 = *(const float4*)(g_R + (size_t)es1.x * 256 + f * 4);
        float4 Yv0 = *(const float4*)(g_Y + (size_t)es0.x * 16 + kq * 4);
        float4 Yv1 = *(const float4*)(g_Y + (size_t)es1.x * 16 + kq * 4);
        float r00, r01, r02, r03, r10, r11, r12, r13;
        if (kq == 0)      { r00 = Rf0.x; r01 = Rf0.y; r02 = Rf0.y; r03 = Rf0.y;
                            r10 = Rf1.x; r11 = Rf1.y; r12 = Rf1.y; r13 = Rf1.y; }
        else if (kq == 1) { r00 = Rf0.z; r01 = Rf0.z; r02 = Rf0.z; r03 = Rf0.z;
                            r10 = Rf1.z; r11 = Rf1.z; r12 = Rf1.z; r13 = Rf1.z; }
        else if (kq == 2) { r00 = Rf0.z; r01 = Rf0.w; r02 = Rf0.w; r03 = Rf0.w;
                            r10 = Rf1.z; r11 = Rf1.w; r12 = Rf1.w; r13 = Rf1.w; }
        else              { r00 = Rf0.w; r01 = Rf0.w; r02 = Rf0.w; r03 = Rf0.w;
                            r10 = Rf1.w; r11 = Rf1.w; r12 = Rf1.w; r13 = Rf1.w; }
        a0 += hs0 * r00 * Yv0.x;
        a1 += hs0 * r01 * Yv0.y;
        a2 += hs0 * r02 * Yv0.z;
        a3 += hs0 * r03 * Yv0.w;
        a0 += hs1 * r10 * Yv1.x;
        a1 += hs1 * r11 * Yv1.y;
        a2 += hs1 * r12 * Yv1.z;
        a3 += hs1 * r13 * Yv1.w;
    }
    if (idx < end) {
        int2 es = g_es[idx];
        float hs = g_h[(size_t)es.y * 64 + f];
        float4 Rf = *(const float4*)(g_R + (size_t)es.x * 256 + f * 4);
        float4 Yv = *(const float4*)(g_Y + (size_t)es.x * 16 + kq * 4);
        float r0, r1, r2, r3;
        if (kq == 0)      { r0 = Rf.x; r1 = Rf.y; r2 = Rf.y; r3 = Rf.y; }
        else if (kq == 1) { r0 = Rf.z; r1 = Rf.z; r2 = Rf.z; r3 = Rf.z; }
        else if (kq == 2) { r0 = Rf.z; r1 = Rf.w; r2 = Rf.w; r3 = Rf.w; }
        else              { r0 = Rf.w; r1 = Rf.w; r2 = Rf.w; r3 = Rf.w; }
        a0 += hs * r0 * Yv.x;
        a1 += hs * r1 * Yv.y;
        a2 += hs * r2 * Yv.z;
        a3 += hs * r3 * Yv.w;
    }
    const float ia = 1.f / 16.f;
    *(float4*)&Asm[f][kq * 4] = make_float4(a0 * ia, a1 * ia, a2 * ia, a3 * ia);
    __syncthreads();

    int g = f;
    float o0 = 0.f, o1 = 0.f, o2 = 0.f, o3 = 0.f;
    if (kq == 0) {
#pragma unroll 4
        for (int ff = 0; ff < 64; ++ff) {
            float4 a = *(const float4*)&Asm[ff][0];
            float w0 = Wmix[ff * 64 + g];
            float w1 = Wmix[4096 + ff * 64 + g];
            o0 += a.x * w0; o1 += a.y * w1; o2 += a.z * w1; o3 += a.w * w1;
        }
    } else if (kq == 1) {
#pragma unroll 4
        for (int ff = 0; ff < 64; ++ff) {
            float4 a = *(const float4*)&Asm[ff][4];
            float w2 = Wmix[8192 + ff * 64 + g];
            o0 += a.x * w2; o1 += a.y * w2; o2 += a.z * w2; o3 += a.w * w2;
        }
    } else if (kq == 2) {
#pragma unroll 4
        for (int ff = 0; ff < 64; ++ff) {
            float4 a = *(const float4*)&Asm[ff][8];
            float w2 = Wmix[8192 + ff * 64 + g];
            float w3 = Wmix[12288 + ff * 64 + g];
            o0 += a.x * w2; o1 += a.y * w3; o2 += a.z * w3; o3 += a.w * w3;
        }
    } else {
#pragma unroll 4
        for (int ff = 0; ff < 64; ++ff) {
            float4 a = *(const float4*)&Asm[ff][12];
            float w3 = Wmix[12288 + ff * 64 + g];
            o0 += a.x * w3; o1 += a.y * w3; o2 += a.z * w3; o3 += a.w * w3;
        }
    }
    if (kq == 0) ss[g] = o0;
    __syncthreads();

    int sp = g_species[n];
    const float* Ws = Wsc + (size_t)sp * 4096;
    float c0 = 0.f, c1 = 0.f, c2v = 0.f, c3v = 0.f;
#pragma unroll 4
    for (int ff = 0; ff < 64; ++ff) {
        float4 a = *(const float4*)&nfs[ff][kq * 4];
        float w = Ws[ff * 64 + g];
        c0 += a.x * w; c1 += a.y * w; c2v += a.z * w; c3v += a.w * w;
    }

    float sv = ss[g];
    float pv = wprod[g] + wprod[64 + g] * sv + wprod[128 + g] * sv * sv;
    float q0 = o0 * pv + c0;
    float q1 = o1 * pv + c1;
    float q2 = o2 * pv + c2v;
    float q3 = o3 * pv + c3v;
    if (last) {
        if (kq != 0) { q0 = q1 = q2 = q3 = 0.f; }
        else { q1 = q2 = q3 = 0.f; }
    }
    size_t base = (size_t)n * 1024 + (size_t)(kq * 4) * 64 + g;
    nf_out[base] = q0;
    nf_out[base + 64] = q1;
    nf_out[base + 128] = q2;
    nf_out[base + 192] = q3;
}

// ---------------- readouts ----------------------------------------------------
__global__ void k_readout(const float* __restrict__ wr, const float* __restrict__ m1,
                          const float* __restrict__ m2, float* __restrict__ out) {
    int n = blockIdx.x;
    int f = threadIdx.x;  // 64
    __shared__ float red[64];
    __shared__ float row2[64];
    __shared__ float tt[16];
    red[f] = g_nfB[(size_t)n * 1024 + f] * wr[f];
    row2[f] = g_nfA[(size_t)n * 1024 + f];
    __syncthreads();
    for (int sdist = 32; sdist > 0; sdist >>= 1) {
        if (f < sdist) red[f] += red[f + sdist];
        __syncthreads();
    }
    if (f == 0) out[2 * n] = red[0];
    if (f < 16) {
        float a = 0.f;
#pragma unroll 8
        for (int ff = 0; ff < 64; ++ff) a += row2[ff] * m1[ff * 16 + f];
        tt[f] = silu_f(a);
    }
    __syncthreads();
    if (f == 0) {
        float a = 0.f;
#pragma unroll
        for (int j = 0; j < 16; ++j) a += tt[j] * m2[j];
        out[2 * n + 1] = a;
    }
}

// ---------------- host launch --------------------------------------------------
extern "C" void kernel_launch(void* const* d_in, const int* in_sizes, int n_in,
                              void* d_out, int out_size) {
    const float* positions = (const float*)d_in[0];
    const float* node_attrs = (const float*)d_in[1];
    const float* shifts = (const float*)d_in[2];
    const int* senders = (const int*)d_in[3];
    const int* receivers = (const int*)d_in[4];
    const float* w_embed = (const float*)d_in[5];

    const float *u_up[2], *u_r1[2], *u_r2[2], *u_r3[2], *u_mix[2], *u_sc[2], *u_prod[2];
    const float *w_read0, *w_mlp1, *w_mlp2;
    u_up[0] = (const float*)d_in[6];
    u_r1[0] = (const float*)d_in[7];
    u_r2[0] = (const float*)d_in[8];
    u_r3[0] = (const float*)d_in[9];
    u_mix[0] = (const float*)d_in[10];
    u_sc[0] = (const float*)d_in[11];
    u_prod[0] = (const float*)d_in[12];
    if (in_sizes[13] == 64) {
        w_read0 = (const float*)d_in[13];
        u_up[1] = (const float*)d_in[14];
        u_r1[1] = (const float*)d_in[15];
        u_r2[1] = (const float*)d_in[16];
        u_r3[1] = (const float*)d_in[17];
        u_mix[1] = (const float*)d_in[18];
        u_sc[1] = (const float*)d_in[19];
        u_prod[1] = (const float*)d_in[20];
        w_mlp1 = (const float*)d_in[21];
        w_mlp2 = (const float*)d_in[22];
    } else {
        u_up[1] = (const float*)d_in[13];
        u_r1[1] = (const float*)d_in[14];
        u_r2[1] = (const float*)d_in[15];
        u_r3[1] = (const float*)d_in[16];
        u_mix[1] = (const float*)d_in[17];
        u_sc[1] = (const float*)d_in[18];
        u_prod[1] = (const float*)d_in[19];
        w_read0 = (const float*)d_in[20];
        w_mlp1 = (const float*)d_in[21];
        w_mlp2 = (const float*)d_in[22];
    }
    float* out = (float*)d_out;

    const int EB = (Ee + 255) / 256;  // 625
    const int NB = (Nn + 255) / 256;  // 40

    // k_radial kept at launch slot 4 = the ncu capture slot.
    k_geom<<<EB, 256>>>(positions, shifts, senders, receivers);
    k_wprep3<<<32, 256>>>(u_r3[0], u_r3[1]);
    k_zero<<<NB, 256>>>();
    k_radial<<<Ee / 64, 256>>>(u_r1[0], u_r2[0], 0);
    k_count<<<EB, 256>>>(receivers);
    k_scan<<<1, 1024>>>();
    k_fill<<<EB, 256>>>(receivers);
    k_sortseg<<<NB, 256>>>();
    k_resolve<<<EB, 256>>>(senders);
    k_embed<<<Nn, 64>>>(node_attrs, w_embed);

    // interaction 0: in = A (embed), out = B
    k_h<<<Nn, 64>>>(0, u_up[0]);
    k_gather<<<Nn, 256>>>(0, u_mix[0], u_sc[0], u_prod[0], 0);

    // interaction 1: in = B, out = A (last -> only k=0 kept)
    k_h<<<Nn, 64>>>(1, u_up[1]);
    k_radial<<<Ee / 64, 256>>>(u_r1[1], u_r2[1], 1);
    k_gather<<<Nn, 256>>>(1, u_mix[1], u_sc[1], u_prod[1], 1);

    k_readout<<<Nn, 64>>>(w_read0, w_mlp1, w_mlp2, out);
}

// round 15
// speedup vs baseline: 1.0647x; 1.0189x over previous
#include <cuda_runtime.h>
#include <math.h>

#define Nn 10000
#define Ee 160000

// ---------------- device scratch (allocation-free rule: __device__ globals) ----
__device__ __align__(16) float g_Y[(size_t)Ee * 16];
__device__ __align__(16) float g_bess[(size_t)Ee * 8];
__device__ __align__(16) float g_R[(size_t)Ee * 256];
__device__ __align__(16) float g_nfA[(size_t)Nn * 1024];
__device__ __align__(16) float g_nfB[(size_t)Nn * 1024];
__device__ __align__(16) float g_h[(size_t)Nn * 64];
__device__ __align__(16) float g_W3p[2][16384];  // paired (col, col+32) fp32 images
__device__ __align__(16) int2 g_es[Ee];          // (edge id, sender id) per CSR slot
__device__ float g_htab[640];                    // h0 table: [species][f]
__device__ int g_species[Nn];
__device__ int g_cnt[Nn];
__device__ int g_cursor[Nn];
__device__ int g_off[Nn + 1];
__device__ int g_eidx[Ee];

__device__ __forceinline__ float silu_f(float x) {
    return __fdividef(x, 1.f + __expf(-x));
}

// ---- packed f32x2 helpers (Blackwell FFMA2; ptxas never auto-fuses these) ----
__device__ __forceinline__ unsigned long long pack2(float x, float y) {
    unsigned long long r;
    asm("mov.b64 %0, {%1, %2};" : "=l"(r) : "f"(x), "f"(y));
    return r;
}
__device__ __forceinline__ void unpack2(unsigned long long v, float& x, float& y) {
    asm("mov.b64 {%0, %1}, %2;" : "=f"(x), "=f"(y) : "l"(v));
}
__device__ __forceinline__ void ffma2(unsigned long long& acc, unsigned long long a,
                                      unsigned long long b) {
    asm("fma.rn.f32x2 %0, %1, %2, %0;" : "+l"(acc) : "l"(a), "l"(b));
}

// ---------------- geometry: Y (l=0..3) + bessel radial basis ------------------
// sin(n*t) via exact Chebyshev recurrence: one sinf+cosf instead of 8 sinf.
__global__ void k_geom(const float* __restrict__ pos, const float* __restrict__ shifts,
                       const int* __restrict__ snd, const int* __restrict__ rcv) {
    int e = blockIdx.x * 256 + threadIdx.x;
    if (e >= Ee) return;
    int s = snd[e], r = rcv[e];
    float x = pos[r * 3 + 0] - pos[s * 3 + 0] + shifts[e * 3 + 0];
    float y = pos[r * 3 + 1] - pos[s * 3 + 1] + shifts[e * 3 + 1];
    float z = pos[r * 3 + 2] - pos[s * 3 + 2] + shifts[e * 3 + 2];
    float rr = sqrtf(x * x + y * y + z * z);
    float inv = 1.f / (rr + 1e-9f);
    float ux = x * inv, uy = y * inv, uz = z * inv;
    const float s3 = 1.7320508075688772f, s5 = 2.2360679774997896f, s7 = 2.6457513110645907f;
    const float s15 = 3.872983346207417f, s42 = 6.48074069840786f;
    const float s70 = 8.366600265340756f, s105 = 10.246950765959598f;
    float Y[16];
    Y[0] = 1.f;
    Y[1] = s3 * ux; Y[2] = s3 * uy; Y[3] = s3 * uz;
    Y[4] = s15 * ux * uy;
    Y[5] = s15 * uy * uz;
    Y[6] = 0.5f * s5 * (3.f * uz * uz - 1.f);
    Y[7] = s15 * ux * uz;
    Y[8] = 0.5f * s15 * (ux * ux - uy * uy);
    Y[9] = 0.25f * s70 * uy * (3.f * ux * ux - uy * uy);
    Y[10] = s105 * ux * uy * uz;
    Y[11] = 0.25f * s42 * uy * (5.f * uz * uz - 1.f);
    Y[12] = 0.5f * s7 * uz * (5.f * uz * uz - 3.f);
    Y[13] = 0.25f * s42 * ux * (5.f * uz * uz - 1.f);
    Y[14] = 0.5f * s105 * uz * (ux * ux - uy * uy);
    Y[15] = 0.25f * s70 * ux * (ux * ux - 3.f * uy * uy);
    float4* yo = (float4*)(g_Y + (size_t)e * 16);
    yo[0] = make_float4(Y[0], Y[1], Y[2], Y[3]);
    yo[1] = make_float4(Y[4], Y[5], Y[6], Y[7]);
    yo[2] = make_float4(Y[8], Y[9], Y[10], Y[11]);
    yo[3] = make_float4(Y[12], Y[13], Y[14], Y[15]);

    float xr = rr * 0.1f;
    float env = 0.f;
    if (xr < 1.f) {
        float x2 = xr * xr;
        float x5 = x2 * x2 * xr;
        env = 1.f - 21.f * x5 + 35.f * x5 * xr - 15.f * x5 * x2;
    }
    const float pref = 0.44721359549995793f;
    const float PIv = 3.14159265358979323846f;
    float t = PIv * rr * 0.1f;
    float s1 = sinf(t), c2 = 2.f * cosf(t);
    float scale = pref * inv * env;
    float sprev = 0.f, sn = s1;
#pragma unroll
    for (int n2 = 1; n2 <= 8; ++n2) {
        g_bess[(size_t)e * 8 + (n2 - 1)] = scale * sn;
        float nx = c2 * sn - sprev;
        sprev = sn;
        sn = nx;
    }
}

// ---------------- W3 prepack: pair columns (c, c+32) for FFMA2 b-operands ------
// layout: pair index = k*128 + j2*32 + tx  <->  cols (tx+64*j2, tx+32+64*j2)
__global__ void k_wprep3(const float* __restrict__ W3a, const float* __restrict__ W3b) {
    int i = blockIdx.x * 256 + threadIdx.x;
    if (i >= 8192) return;
    int k = i >> 7, p = i & 127;
    int j2 = p >> 5, tx = p & 31;
#pragma unroll
    for (int u = 0; u < 2; ++u) {
        const float* W3 = u ? W3b : W3a;
        g_W3p[u][2 * i] = W3[k * 256 + tx + 64 * j2];
        g_W3p[u][2 * i + 1] = W3[k * 256 + tx + 32 + 64 * j2];
    }
}

// ---------------- CSR build (deterministic: per-segment sorted) ---------------
__global__ void k_zero() {
    int i = blockIdx.x * 256 + threadIdx.x;
    if (i < Nn) { g_cnt[i] = 0; g_cursor[i] = 0; }
}
__global__ void k_count(const int* __restrict__ rcv) {
    int e = blockIdx.x * 256 + threadIdx.x;
    if (e < Ee) atomicAdd(&g_cnt[rcv[e]], 1);
}
__global__ void k_scan() {  // 1 block, 1024 threads; warp-shuffle scan, 10 nodes/thread
    int tid = threadIdx.x;
    int base = tid * 10;
    int v[10];
    int s = 0;
#pragma unroll
    for (int j = 0; j < 10; ++j) {
        int i = base + j;
        int c = (i < Nn) ? g_cnt[i] : 0;
        v[j] = s;
        s += c;
    }
    int lane = tid & 31, w = tid >> 5;
    int x = s;
#pragma unroll
    for (int d = 1; d < 32; d <<= 1) {
        int t = __shfl_up_sync(0xffffffffu, x, d);
        if (lane >= d) x += t;
    }
    __shared__ int ws[32];
    if (lane == 31) ws[w] = x;
    __syncthreads();
    if (w == 0) {
        int y = ws[lane];
#pragma unroll
        for (int d = 1; d < 32; d <<= 1) {
            int t = __shfl_up_sync(0xffffffffu, y, d);
            if (lane >= d) y += t;
        }
        ws[lane] = y;
    }
    __syncthreads();
    int excl = x - s + (w > 0 ? ws[w - 1] : 0);
#pragma unroll
    for (int j = 0; j < 10; ++j) {
        int i = base + j;
        if (i < Nn) g_off[i] = excl + v[j];
    }
    if (tid == 1023) g_off[Nn] = ws[31];
}
__global__ void k_fill(const int* __restrict__ rcv) {
    int e = blockIdx.x * 256 + threadIdx.x;
    if (e >= Ee) return;
    int r = rcv[e];
    int p = atomicAdd(&g_cursor[r], 1);
    g_eidx[g_off[r] + p] = e;
}
// sort each segment in a per-thread local array (L1) instead of global memory
__global__ void k_sortseg() {
    int n = blockIdx.x * 256 + threadIdx.x;
    if (n >= Nn) return;
    int b = g_off[n], t = g_off[n + 1];
    int deg = t - b;
    if (deg <= 64) {
        int loc[64];
        for (int i = 0; i < deg; ++i) loc[i] = g_eidx[b + i];
        for (int i = 1; i < deg; ++i) {
            int key = loc[i];
            int j = i - 1;
            while (j >= 0 && loc[j] > key) { loc[j + 1] = loc[j]; --j; }
            loc[j + 1] = key;
        }
        for (int i = 0; i < deg; ++i) g_eidx[b + i] = loc[i];
    } else {
        for (int i = b + 1; i < t; ++i) {
            int key = g_eidx[i];
            int j = i - 1;
            while (j >= b && g_eidx[j] > key) { g_eidx[j + 1] = g_eidx[j]; --j; }
            g_eidx[j + 1] = key;
        }
    }
}
__global__ void k_resolve(const int* __restrict__ snd) {
    int i = blockIdx.x * 256 + threadIdx.x;
    if (i < Ee) {
        int e = g_eidx[i];
        g_es[i] = make_int2(e, snd[e]);
    }
}

// ---------------- node embedding + species index ------------------------------
__global__ void k_embed(const float* __restrict__ attrs, const float* __restrict__ wemb) {
    int n = blockIdx.x;
    int f = threadIdx.x;  // 64
    __shared__ int sp;
    if (f == 0) {
        int s = 0;
#pragma unroll
        for (int j = 0; j < 10; ++j)
            if (attrs[n * 10 + j] > 0.5f) s = j;
        sp = s;
        g_species[n] = s;
    }
    __syncthreads();
    g_nfA[(size_t)n * 1024 + f] = wemb[sp * 64 + f];
#pragma unroll
    for (int k = 1; k < 16; ++k) g_nfA[(size_t)n * 1024 + k * 64 + f] = 0.f;
}

// ---------------- interaction-0 h: 10-row table (h0 = w_embed @ W_up) ----------
__global__ void k_htab(const float* __restrict__ wemb, const float* __restrict__ Wup) {
    int i = blockIdx.x * 256 + threadIdx.x;
    if (i >= 640) return;
    int sp = i >> 6, f = i & 63;
    float acc = 0.f;
#pragma unroll 8
    for (int g = 0; g < 64; ++g) acc += wemb[sp * 64 + g] * Wup[g * 64 + f];
    g_htab[i] = acc;
}
__global__ void k_hlut() {
    int i = blockIdx.x * 256 + threadIdx.x;
    if (i < Nn * 64) {
        int n = i >> 6, f = i & 63;
        g_h[i] = g_htab[g_species[n] * 64 + f];
    }
}

// ---------------- h = nf[:,:,0] @ W_up (generic, interaction 1) ---------------
__global__ void k_h(int src, const float* __restrict__ Wup) {
    const float* nf = src ? g_nfB : g_nfA;
    int n = blockIdx.x;
    int f = threadIdx.x;  // 64
    __shared__ float row[64];
    row[f] = nf[(size_t)n * 1024 + f];
    __syncthreads();
    float acc = 0.f;
#pragma unroll 8
    for (int g = 0; g < 64; ++g) acc += row[g] * Wup[g * 64 + f];
    g_h[(size_t)n * 64 + f] = acc;
}

// ---------------- radial MLP: bess[E,8] -> silu -> silu -> R[E,256] -----------
// 64 edges/block, 256 threads. Static smem 29952 B -> 3 blocks/SM.
// t1/t2 SHARE one transposed buffer ([col][edge], pad 68).
__global__ void __launch_bounds__(256, 3) k_radial(const float* __restrict__ W1,
                                                   const float* __restrict__ W2, int u) {
    __shared__ __align__(16) float smem_f[7488];
    float* sb = smem_f;                                   // [64][9]   576
    float* w1s = smem_f + 576;                            // [8][64]   512
    float(*tt)[68] = (float(*)[68])(smem_f + 1088);       // [64][68]  4352 (t1 then t2)
    float* wch = smem_f + 5440;                           // 2048 (8 KB chunk)
    int tid = threadIdx.x;
    int e0 = blockIdx.x * 64;

    {   // stage bess tile (padded rows) + W1
        for (int i = tid; i < 512; i += 256) {
            int e = i >> 3, j = i & 7;
            sb[e * 9 + j] = g_bess[(size_t)e0 * 8 + i];
        }
        for (int i = tid; i < 512; i += 256) w1s[i] = W1[i];
    }
    __syncthreads();

    // layer 1: [64,8]@[8,64] -> silu -> tt[c][e]  (t1 phase)
#pragma unroll
    for (int i = 0; i < 16; ++i) {
        int o = tid + 256 * i;
        int e = o >> 6, c = o & 63;
        float acc = 0.f;
#pragma unroll
        for (int j = 0; j < 8; ++j) acc += sb[e * 9 + j] * w1s[j * 64 + c];
        tt[c][e] = silu_f(acc);
    }

    // layer 2: [64,64]@[64,64]. 4x4 register tiles (FFMA2 pairs), acc in regs.
    int ty2 = tid >> 4, tx2 = tid & 15;
    unsigned long long c2p[4][2] = {};
    for (int kc = 0; kc < 2; ++kc) {
        __syncthreads();
        {
            float4* d = (float4*)wch;
            const float4* s4 = ((const float4*)W2) + kc * 512;
            for (int i = tid; i < 512; i += 256) d[i] = s4[i];
        }
        __syncthreads();
#pragma unroll
        for (int kk = 0; kk < 32; ++kk) {
            int k = kc * 32 + kk;
            const unsigned long long* bp2 =
                (const unsigned long long*)&wch[kk * 64 + tx2 * 4];
            unsigned long long b01 = bp2[0];
            unsigned long long b23 = bp2[1];
            float4 av = *(const float4*)&tt[k][ty2 * 4];
            float a_[4] = {av.x, av.y, av.z, av.w};
#pragma unroll
            for (int j = 0; j < 4; ++j) {
                unsigned long long aa = pack2(a_[j], a_[j]);
                ffma2(c2p[j][0], aa, b01);
                ffma2(c2p[j][1], aa, b23);
            }
        }
    }
    __syncthreads();  // all t1 reads done -> safe to overwrite tt with t2
#pragma unroll
    for (int j = 0; j < 4; ++j) {
        float v0, v1, v2, v3;
        unpack2(c2p[j][0], v0, v1);
        unpack2(c2p[j][1], v2, v3);
        tt[tx2 * 4 + 0][ty2 * 4 + j] = silu_f(v0);
        tt[tx2 * 4 + 1][ty2 * 4 + j] = silu_f(v1);
        tt[tx2 * 4 + 2][ty2 * 4 + j] = silu_f(v2);
        tt[tx2 * 4 + 3][ty2 * 4 + j] = silu_f(v3);
    }

    // layer 3: [64,64]@[64,256] -> R. 8 edges x 4 col-pairs per thread.
    int ty = tid >> 5, tx = tid & 31;
    unsigned long long c3p[8][4] = {};
    for (int kc = 0; kc < 8; ++kc) {
        __syncthreads();
        {
            float4* d = (float4*)wch;
            const float4* s4 = ((const float4*)(g_W3p[u])) + kc * 512;
            for (int i = tid; i < 512; i += 256) d[i] = s4[i];
        }
        __syncthreads();
        const unsigned long long* wp = (const unsigned long long*)wch;
#pragma unroll
        for (int kk = 0; kk < 8; ++kk) {
            int k = kc * 8 + kk;
            unsigned long long bp[4];
#pragma unroll
            for (int j2 = 0; j2 < 4; ++j2) bp[j2] = wp[kk * 128 + j2 * 32 + tx];
            float4 a01 = *(const float4*)&tt[k][ty * 8];
            float4 a23 = *(const float4*)&tt[k][ty * 8 + 4];
            float a_[8] = {a01.x, a01.y, a01.z, a01.w, a23.x, a23.y, a23.z, a23.w};
#pragma unroll
            for (int je = 0; je < 8; ++je) {
                unsigned long long aa = pack2(a_[je], a_[je]);
#pragma unroll
                for (int j2 = 0; j2 < 4; ++j2) ffma2(c3p[je][j2], aa, bp[j2]);
            }
        }
    }
#pragma unroll
    for (int je = 0; je < 8; ++je) {
        size_t rb = ((size_t)(e0 + ty * 8 + je)) * 256;
#pragma unroll
        for (int j2 = 0; j2 < 4; ++j2) {
            float lo, hi;
            unpack2(c3p[je][j2], lo, hi);
            g_R[rb + tx + 64 * j2] = lo;
            g_R[rb + tx + 32 + 64 * j2] = hi;
        }
    }
}

// ---------------- gather + mix + product + self-connection --------------------
// One block per node. 256 threads: f = tid&63, kq = tid>>6.
// Edge loop unrolled x2 over packed (edge, sender) stream.
// L_OF = [0,1,1,1, 2,2,2,2, 2,3,3,3, 3,3,3,3]
__global__ void __launch_bounds__(256) k_gather(int src, const float* __restrict__ Wmix,
                                                const float* __restrict__ Wsc,
                                                const float* __restrict__ wprod,
                                                int last) {
    const float* nf_in = src ? g_nfB : g_nfA;
    float* nf_out = src ? g_nfA : g_nfB;
    int n = blockIdx.x;
    int tid = threadIdx.x;
    int f = tid & 63;
    int kq = tid >> 6;  // warp-uniform

    __shared__ __align__(16) float Asm[64][20];
    __shared__ __align__(16) float nfs[64][20];
    __shared__ float ss[64];

    for (int i = tid; i < 1024; i += 256) {
        int k = i >> 6, ff = i & 63;
        nfs[ff][k] = nf_in[(size_t)n * 1024 + i];
    }

    float a0 = 0.f, a1 = 0.f, a2 = 0.f, a3 = 0.f;
    int beg = g_off[n], end = g_off[n + 1];
    int idx = beg;
    for (; idx + 1 < end; idx += 2) {
        int2 es0 = g_es[idx];
        int2 es1 = g_es[idx + 1];
        float hs0 = g_h[(size_t)es0.y * 64 + f];
        float hs1 = g_h[(size_t)es1.y * 64 + f];
        float4 Rf0 = *(const float4*)(g_R + (size_t)es0.x * 256 + f * 4);
        float4 Rf1 = *(const float4*)(g_R + (size_t)es1.x * 256 + f * 4);
        float4 Yv0 = *(const float4*)(g_Y + (size_t)es0.x * 16 + kq * 4);
        float4 Yv1 = *(const float4*)(g_Y + (size_t)es1.x * 16 + kq * 4);
        float r00, r01, r02, r03, r10, r11, r12, r13;
        if (kq == 0)      { r00 = Rf0.x; r01 = Rf0.y; r02 = Rf0.y; r03 = Rf0.y;
                            r10 = Rf1.x; r11 = Rf1.y; r12 = Rf1.y; r13 = Rf1.y; }
        else if (kq == 1) { r00 = Rf0.z; r01 = Rf0.z; r02 = Rf0.z; r03 = Rf0.z;
                            r10 = Rf1.z; r11 = Rf1.z; r12 = Rf1.z; r13 = Rf1.z; }
        else if (kq == 2) { r00 = Rf0.z; r01 = Rf0.w; r02 = Rf0.w; r03 = Rf0.w;
                            r10 = Rf1.z; r11 = Rf1.w; r12 = Rf1.w; r13 = Rf1.w; }
        else              { r00 = Rf0.w; r01 = Rf0.w; r02 = Rf0.w; r03 = Rf0.w;
                            r10 = Rf1.w; r11 = Rf1.w; r12 = Rf1.w; r13 = Rf1.w; }
        a0 += hs0 * r00 * Yv0.x;
        a1 += hs0 * r01 * Yv0.y;
        a2 += hs0 * r02 * Yv0.z;
        a3 += hs0 * r03 * Yv0.w;
        a0 += hs1 * r10 * Yv1.x;
        a1 += hs1 * r11 * Yv1.y;
        a2 += hs1 * r12 * Yv1.z;
        a3 += hs1 * r13 * Yv1.w;
    }
    if (idx < end) {
        int2 es = g_es[idx];
        float hs = g_h[(size_t)es.y * 64 + f];
        float4 Rf = *(const float4*)(g_R + (size_t)es.x * 256 + f * 4);
        float4 Yv = *(const float4*)(g_Y + (size_t)es.x * 16 + kq * 4);
        float r0, r1, r2, r3;
        if (kq == 0)      { r0 = Rf.x; r1 = Rf.y; r2 = Rf.y; r3 = Rf.y; }
        else if (kq == 1) { r0 = Rf.z; r1 = Rf.z; r2 = Rf.z; r3 = Rf.z; }
        else if (kq == 2) { r0 = Rf.z; r1 = Rf.w; r2 = Rf.w; r3 = Rf.w; }
        else              { r0 = Rf.w; r1 = Rf.w; r2 = Rf.w; r3 = Rf.w; }
        a0 += hs * r0 * Yv.x;
        a1 += hs * r1 * Yv.y;
        a2 += hs * r2 * Yv.z;
        a3 += hs * r3 * Yv.w;
    }
    const float ia = 1.f / 16.f;
    *(float4*)&Asm[f][kq * 4] = make_float4(a0 * ia, a1 * ia, a2 * ia, a3 * ia);
    __syncthreads();

    int g = f;
    float o0 = 0.f, o1 = 0.f, o2 = 0.f, o3 = 0.f;
    if (kq == 0) {
#pragma unroll 4
        for (int ff = 0; ff < 64; ++ff) {
            float4 a = *(const float4*)&Asm[ff][0];
            float w0 = Wmix[ff * 64 + g];
            float w1 = Wmix[4096 + ff * 64 + g];
            o0 += a.x * w0; o1 += a.y * w1; o2 += a.z * w1; o3 += a.w * w1;
        }
    } else if (kq == 1) {
#pragma unroll 4
        for (int ff = 0; ff < 64; ++ff) {
            float4 a = *(const float4*)&Asm[ff][4];
            float w2 = Wmix[8192 + ff * 64 + g];
            o0 += a.x * w2; o1 += a.y * w2; o2 += a.z * w2; o3 += a.w * w2;
        }
    } else if (kq == 2) {
#pragma unroll 4
        for (int ff = 0; ff < 64; ++ff) {
            float4 a = *(const float4*)&Asm[ff][8];
            float w2 = Wmix[8192 + ff * 64 + g];
            float w3 = Wmix[12288 + ff * 64 + g];
            o0 += a.x * w2; o1 += a.y * w3; o2 += a.z * w3; o3 += a.w * w3;
        }
    } else {
#pragma unroll 4
        for (int ff = 0; ff < 64; ++ff) {
            float4 a = *(const float4*)&Asm[ff][12];
            float w3 = Wmix[12288 + ff * 64 + g];
            o0 += a.x * w3; o1 += a.y * w3; o2 += a.z * w3; o3 += a.w * w3;
        }
    }
    if (kq == 0) ss[g] = o0;
    __syncthreads();

    int sp = g_species[n];
    const float* Ws = Wsc + (size_t)sp * 4096;
    float c0 = 0.f, c1 = 0.f, c2v = 0.f, c3v = 0.f;
#pragma unroll 4
    for (int ff = 0; ff < 64; ++ff) {
        float4 a = *(const float4*)&nfs[ff][kq * 4];
        float w = Ws[ff * 64 + g];
        c0 += a.x * w; c1 += a.y * w; c2v += a.z * w; c3v += a.w * w;
    }

    float sv = ss[g];
    float pv = wprod[g] + wprod[64 + g] * sv + wprod[128 + g] * sv * sv;
    float q0 = o0 * pv + c0;
    float q1 = o1 * pv + c1;
    float q2 = o2 * pv + c2v;
    float q3 = o3 * pv + c3v;
    if (last) {
        if (kq != 0) { q0 = q1 = q2 = q3 = 0.f; }
        else { q1 = q2 = q3 = 0.f; }
    }
    size_t base = (size_t)n * 1024 + (size_t)(kq * 4) * 64 + g;
    nf_out[base] = q0;
    nf_out[base + 64] = q1;
    nf_out[base + 128] = q2;
    nf_out[base + 192] = q3;
}

// ---------------- readouts ----------------------------------------------------
__global__ void k_readout(const float* __restrict__ wr, const float* __restrict__ m1,
                          const float* __restrict__ m2, float* __restrict__ out) {
    int n = blockIdx.x;
    int f = threadIdx.x;  // 64
    __shared__ float red[64];
    __shared__ float row2[64];
    __shared__ float tt[16];
    red[f] = g_nfB[(size_t)n * 1024 + f] * wr[f];
    row2[f] = g_nfA[(size_t)n * 1024 + f];
    __syncthreads();
    for (int sdist = 32; sdist > 0; sdist >>= 1) {
        if (f < sdist) red[f] += red[f + sdist];
        __syncthreads();
    }
    if (f == 0) out[2 * n] = red[0];
    if (f < 16) {
        float a = 0.f;
#pragma unroll 8
        for (int ff = 0; ff < 64; ++ff) a += row2[ff] * m1[ff * 16 + f];
        tt[f] = silu_f(a);
    }
    __syncthreads();
    if (f == 0) {
        float a = 0.f;
#pragma unroll
        for (int j = 0; j < 16; ++j) a += tt[j] * m2[j];
        out[2 * n + 1] = a;
    }
}

// ---------------- host launch --------------------------------------------------
extern "C" void kernel_launch(void* const* d_in, const int* in_sizes, int n_in,
                              void* d_out, int out_size) {
    const float* positions = (const float*)d_in[0];
    const float* node_attrs = (const float*)d_in[1];
    const float* shifts = (const float*)d_in[2];
    const int* senders = (const int*)d_in[3];
    const int* receivers = (const int*)d_in[4];
    const float* w_embed = (const float*)d_in[5];

    const float *u_up[2], *u_r1[2], *u_r2[2], *u_r3[2], *u_mix[2], *u_sc[2], *u_prod[2];
    const float *w_read0, *w_mlp1, *w_mlp2;
    u_up[0] = (const float*)d_in[6];
    u_r1[0] = (const float*)d_in[7];
    u_r2[0] = (const float*)d_in[8];
    u_r3[0] = (const float*)d_in[9];
    u_mix[0] = (const float*)d_in[10];
    u_sc[0] = (const float*)d_in[11];
    u_prod[0] = (const float*)d_in[12];
    if (in_sizes[13] == 64) {
        w_read0 = (const float*)d_in[13];
        u_up[1] = (const float*)d_in[14];
        u_r1[1] = (const float*)d_in[15];
        u_r2[1] = (const float*)d_in[16];
        u_r3[1] = (const float*)d_in[17];
        u_mix[1] = (const float*)d_in[18];
        u_sc[1] = (const float*)d_in[19];
        u_prod[1] = (const float*)d_in[20];
        w_mlp1 = (const float*)d_in[21];
        w_mlp2 = (const float*)d_in[22];
    } else {
        u_up[1] = (const float*)d_in[13];
        u_r1[1] = (const float*)d_in[14];
        u_r2[1] = (const float*)d_in[15];
        u_r3[1] = (const float*)d_in[16];
        u_mix[1] = (const float*)d_in[17];
        u_sc[1] = (const float*)d_in[18];
        u_prod[1] = (const float*)d_in[19];
        w_read0 = (const float*)d_in[20];
        w_mlp1 = (const float*)d_in[21];
        w_mlp2 = (const float*)d_in[22];
    }
    float* out = (float*)d_out;

    const int EB = (Ee + 255) / 256;  // 625
    const int NB = (Nn + 255) / 256;  // 40

    // k_radial kept at launch slot 4 = the ncu capture slot (control).
    k_geom<<<EB, 256>>>(positions, shifts, senders, receivers);
    k_wprep3<<<32, 256>>>(u_r3[0], u_r3[1]);
    k_zero<<<NB, 256>>>();
    k_radial<<<Ee / 64, 256>>>(u_r1[0], u_r2[0], 0);
    k_count<<<EB, 256>>>(receivers);
    k_scan<<<1, 1024>>>();
    k_fill<<<EB, 256>>>(receivers);
    k_sortseg<<<NB, 256>>>();
    k_resolve<<<EB, 256>>>(senders);
    k_embed<<<Nn, 64>>>(node_attrs, w_embed);

    // interaction 0: h via 10-row species table
    k_htab<<<3, 256>>>(w_embed, u_up[0]);
    k_hlut<<<(Nn * 64 + 255) / 256, 256>>>();
    k_gather<<<Nn, 256>>>(0, u_mix[0], u_sc[0], u_prod[0], 0);

    // interaction 1: in = B, out = A (last -> only k=0 kept)
    k_h<<<Nn, 64>>>(1, u_up[1]);
    k_radial<<<Ee / 64, 256>>>(u_r1[1], u_r2[1], 1);
    k_gather<<<Nn, 256>>>(1, u_mix[1], u_sc[1], u_prod[1], 1);

    k_readout<<<Nn, 64>>>(w_read0, w_mlp1, w_mlp2, out);
}